// round 2
// baseline (speedup 1.0000x reference)
#include <cuda_runtime.h>
#include <math.h>

#define NB 1024
#define NS 1024
#define DI 128
#define DS 64
#define KSEL 8

typedef unsigned long long ull;

// Scratch (device globals: allocation-free per harness rules)
__device__ float g_H[(size_t)NB * NS * DS];       // 256 MB
__device__ float g_scores[(size_t)NB * NS];       // 4 MB

// ---- packed f32x2 helpers (FFMA2: 2x fp32 FMA throughput on sm_103a) ----
__device__ __forceinline__ ull fma2(ull a, ull b, ull c) {
    ull d;
    asm("fma.rn.f32x2 %0, %1, %2, %3;" : "=l"(d) : "l"(a), "l"(b), "l"(c));
    return d;
}
__device__ __forceinline__ float lo2(ull v) { return __uint_as_float((unsigned int)v); }
__device__ __forceinline__ float hi2(ull v) { return __uint_as_float((unsigned int)(v >> 32)); }
__device__ __forceinline__ ull pack2(float lo, float hi) {
    return (ull)__float_as_uint(lo) | ((ull)__float_as_uint(hi) << 32);
}

// ============================================================================
// K1: fused MLP (two GEMMs) + per-row score. BM=128 rows per block, 256 thr.
// Per-thread tile: 8 rows x 4 cols. All f32x2 FMA; weights pre-duplicated
// as (w,w) float2 pairs in SMEM so LDS.128 delivers 2 broadcast operands
// with zero MOV construction.
// ============================================================================
static constexpr int BM = 128;
static constexpr int BK = 16;
static constexpr int XST = 130;   // padded row stride (even -> 8B-aligned pairs)

// dynamic smem layout (bytes)
//  XsT : float [BK][XST]   @ 0      (8320)
//  W1d : float2[BK][DS]    @ 8320   (8192)
//  W2d : float2[DS][DS]    @ 16512  (32768)
//  TsT : float [DS][XST]   @ 49280  (33280)
//  qms : float [DS]        @ 82560  (256)
static constexpr int SM_XST  = 0;
static constexpr int SM_W1D  = 8320;
static constexpr int SM_W2D  = 16512;
static constexpr int SM_TST  = 49280;
static constexpr int SM_QMS  = 82560;
static constexpr int SM_TOTAL = 82816;

__global__ __launch_bounds__(256, 2) void k1_mlp(
    const float* __restrict__ X, const float* __restrict__ W1,
    const float* __restrict__ b1, const float* __restrict__ W2,
    const float* __restrict__ b2, const float* __restrict__ q, int blk0)
{
    extern __shared__ __align__(16) char sm[];
    float  (*XsT)[XST] = (float (*)[XST])(sm + SM_XST);
    float2 (*W1d)[DS]  = (float2(*)[DS])(sm + SM_W1D);
    float2 (*W2d)[DS]  = (float2(*)[DS])(sm + SM_W2D);
    float  (*TsT)[XST] = (float (*)[XST])(sm + SM_TST);
    float* qms = (float*)(sm + SM_QMS);

    const int tid = threadIdx.x;
    const int tx = tid & 15;     // 16 col-groups of 4 -> 64 cols
    const int ty = tid >> 4;     // 16 row-groups of 8 -> 128 rows
    const size_t row0 = (size_t)(blockIdx.x + blk0) * BM;

    // ---- preload duplicated W2 and head-mean q ----
    #pragma unroll
    for (int u = 0; u < 4; u++) {
        int idx = tid + 256 * u;                 // float4 index into W2 (1024 total)
        float4 w = ((const float4*)W2)[idx];
        int kk = (idx * 4) >> 6, c = (idx * 4) & 63;
        W2d[kk][c + 0] = make_float2(w.x, w.x);
        W2d[kk][c + 1] = make_float2(w.y, w.y);
        W2d[kk][c + 2] = make_float2(w.z, w.z);
        W2d[kk][c + 3] = make_float2(w.w, w.w);
    }
    if (tid < DS) qms[tid] = 0.5f * (q[tid] + q[DS + tid]);

    ull acc[4][4];
    #pragma unroll
    for (int p = 0; p < 4; p++)
        #pragma unroll
        for (int c = 0; c < 4; c++) acc[p][c] = 0ULL;

    // X-tile loader mapping: 512 float4 per tile, 2 per thread
    const int xr0 = tid >> 2;          // 0..63 (second load: +64)
    const int xc4 = tid & 3;           // k-subgroup
    const int wkk = tid >> 4;          // W1 tile row
    const int wc0 = (tid & 15) * 4;    // W1 col start

    float4 xA, xB, wA;
    // prefetch tile 0
    xA = *(const float4*)(X + (row0 + xr0) * DI + 0 + xc4 * 4);
    xB = *(const float4*)(X + (row0 + xr0 + 64) * DI + 0 + xc4 * 4);
    wA = *(const float4*)(W1 + (size_t)(0 + wkk) * DS + wc0);

    // ---- GEMM1: T = relu(X @ W1 + b1), K = 128 in 8 tiles of 16 ----
    for (int t = 0; t < 8; t++) {
        __syncthreads();
        XsT[xc4 * 4 + 0][xr0] = xA.x;  XsT[xc4 * 4 + 0][xr0 + 64] = xB.x;
        XsT[xc4 * 4 + 1][xr0] = xA.y;  XsT[xc4 * 4 + 1][xr0 + 64] = xB.y;
        XsT[xc4 * 4 + 2][xr0] = xA.z;  XsT[xc4 * 4 + 2][xr0 + 64] = xB.z;
        XsT[xc4 * 4 + 3][xr0] = xA.w;  XsT[xc4 * 4 + 3][xr0 + 64] = xB.w;
        W1d[wkk][wc0 + 0] = make_float2(wA.x, wA.x);
        W1d[wkk][wc0 + 1] = make_float2(wA.y, wA.y);
        W1d[wkk][wc0 + 2] = make_float2(wA.z, wA.z);
        W1d[wkk][wc0 + 3] = make_float2(wA.w, wA.w);
        __syncthreads();

        if (t < 7) {   // prefetch next tile while computing this one
            int k0 = (t + 1) * BK;
            xA = *(const float4*)(X + (row0 + xr0) * DI + k0 + xc4 * 4);
            xB = *(const float4*)(X + (row0 + xr0 + 64) * DI + k0 + xc4 * 4);
            wA = *(const float4*)(W1 + (size_t)(k0 + wkk) * DS + wc0);
        }

        #pragma unroll
        for (int kk = 0; kk < BK; kk++) {
            ull a[4];
            #pragma unroll
            for (int p = 0; p < 4; p++)
                a[p] = *(const ull*)&XsT[kk][ty * 8 + 2 * p];
            ulonglong2 b01 = *(const ulonglong2*)&W1d[kk][tx * 4];
            ulonglong2 b23 = *(const ulonglong2*)&W1d[kk][tx * 4 + 2];
            #pragma unroll
            for (int p = 0; p < 4; p++) {
                acc[p][0] = fma2(a[p], b01.x, acc[p][0]);
                acc[p][1] = fma2(a[p], b01.y, acc[p][1]);
                acc[p][2] = fma2(a[p], b23.x, acc[p][2]);
                acc[p][3] = fma2(a[p], b23.y, acc[p][3]);
            }
        }
    }

    // bias + relu -> TsT (transposed [hidden][row], pair stores)
    {
        float4 b1v = *(const float4*)(b1 + tx * 4);
        float bb[4] = {b1v.x, b1v.y, b1v.z, b1v.w};
        __syncthreads();
        #pragma unroll
        for (int p = 0; p < 4; p++)
            #pragma unroll
            for (int c = 0; c < 4; c++) {
                float lo = fmaxf(lo2(acc[p][c]) + bb[c], 0.0f);
                float hi = fmaxf(hi2(acc[p][c]) + bb[c], 0.0f);
                *(ull*)&TsT[tx * 4 + c][ty * 8 + 2 * p] = pack2(lo, hi);
                acc[p][c] = 0ULL;
            }
    }
    __syncthreads();

    // ---- GEMM2: H = T @ W2 + b2, K = 64 ----
    #pragma unroll 16
    for (int kk = 0; kk < DS; kk++) {
        ull a[4];
        #pragma unroll
        for (int p = 0; p < 4; p++)
            a[p] = *(const ull*)&TsT[kk][ty * 8 + 2 * p];
        ulonglong2 b01 = *(const ulonglong2*)&W2d[kk][tx * 4];
        ulonglong2 b23 = *(const ulonglong2*)&W2d[kk][tx * 4 + 2];
        #pragma unroll
        for (int p = 0; p < 4; p++) {
            acc[p][0] = fma2(a[p], b01.x, acc[p][0]);
            acc[p][1] = fma2(a[p], b01.y, acc[p][1]);
            acc[p][2] = fma2(a[p], b23.x, acc[p][2]);
            acc[p][3] = fma2(a[p], b23.y, acc[p][3]);
        }
    }

    // epilogue: bias, write H, per-row scores
    float4 b2v = *(const float4*)(b2 + tx * 4);
    float bb2[4] = {b2v.x, b2v.y, b2v.z, b2v.w};
    float q0 = qms[tx * 4 + 0], q1 = qms[tx * 4 + 1];
    float q2 = qms[tx * 4 + 2], q3 = qms[tx * 4 + 3];

    #pragma unroll
    for (int p = 0; p < 4; p++) {
        float hl[4], hh[4];
        #pragma unroll
        for (int c = 0; c < 4; c++) {
            hl[c] = lo2(acc[p][c]) + bb2[c];
            hh[c] = hi2(acc[p][c]) + bb2[c];
        }
        size_t re = row0 + ty * 8 + 2 * p;
        *(float4*)&g_H[re * DS + tx * 4]       = make_float4(hl[0], hl[1], hl[2], hl[3]);
        *(float4*)&g_H[(re + 1) * DS + tx * 4] = make_float4(hh[0], hh[1], hh[2], hh[3]);

        float ve = hl[0] * q0 + hl[1] * q1 + hl[2] * q2 + hl[3] * q3;
        float vo = hh[0] * q0 + hh[1] * q1 + hh[2] * q2 + hh[3] * q3;
        // reduce across the 16 lanes sharing ty (lanes [0..15] / [16..31])
        #pragma unroll
        for (int m = 8; m > 0; m >>= 1) {
            ve += __shfl_xor_sync(0xffffffffu, ve, m);
            vo += __shfl_xor_sync(0xffffffffu, vo, m);
        }
        if (tx == 0) {
            g_scores[re]     = ve * 0.125f;
            g_scores[re + 1] = vo * 0.125f;
        }
    }
}

// ============================================================================
// K2: per-batch masked softmax + ctx + top-8 + gather. One block per batch.
// ============================================================================
__global__ __launch_bounds__(256) void k2_attn(
    const float* __restrict__ mask,
    float* __restrict__ out_sel, float* __restrict__ out_ctx,
    float* __restrict__ out_attn)
{
    __shared__ float sms[NS];
    __shared__ float ss[NS];
    __shared__ float aw[NS];
    __shared__ float red[256];
    __shared__ int   redi[256];
    __shared__ float cpart[4][DS];
    __shared__ int   idxs[KSEL];

    const int t = threadIdx.x;
    const int b = blockIdx.x;
    const float* sc = g_scores + (size_t)b * NS;
    const float* mk = mask + (size_t)b * NS;

    float lmax = -INFINITY;
    #pragma unroll
    for (int u = 0; u < 4; u++) {
        int s = t + 256 * u;
        float v = sc[s];
        float m = (mk[s] > 0.5f) ? v : -INFINITY;
        sms[s] = m;
        lmax = fmaxf(lmax, m);
    }
    red[t] = lmax;
    __syncthreads();
    for (int off = 128; off > 0; off >>= 1) {
        if (t < off) red[t] = fmaxf(red[t], red[t + off]);
        __syncthreads();
    }
    const float mx = red[0];
    const bool allm = !(mx > -INFINITY);
    __syncthreads();

    float lsum = 0.0f;
    #pragma unroll
    for (int u = 0; u < 4; u++) {
        int s = t + 256 * u;
        float m = sms[s];
        float e;
        if (allm)                e = 1.0f;
        else if (m == -INFINITY) e = 0.0f;
        else                     e = expf(m - mx);
        aw[s] = e;
        lsum += e;
    }
    red[t] = lsum;
    __syncthreads();
    for (int off = 128; off > 0; off >>= 1) {
        if (t < off) red[t] += red[t + off];
        __syncthreads();
    }
    const float inv = 1.0f / red[0];
    __syncthreads();
    #pragma unroll
    for (int u = 0; u < 4; u++) {
        int s = t + 256 * u;
        float w = aw[s] * inv;
        aw[s] = w;
        out_attn[(size_t)b * NS + s] = w;
        ss[s] = allm ? 0.0f : sms[s];
    }
    __syncthreads();

    const float* Hb = g_H + (size_t)b * NS * DS;
    {
        const int d = t & 63, part = t >> 6;
        float acc = 0.0f;
        const int s0 = part * 256;
        #pragma unroll 8
        for (int s = s0; s < s0 + 256; s++)
            acc += aw[s] * Hb[(size_t)s * DS + d];
        cpart[part][d] = acc;
    }
    __syncthreads();
    if (t < DS)
        out_ctx[(size_t)b * DS + t] =
            (cpart[0][t] + cpart[1][t]) + (cpart[2][t] + cpart[3][t]);

    for (int it = 0; it < KSEL; it++) {
        float bv = -INFINITY; int bi = 0x7fffffff;
        #pragma unroll
        for (int u = 0; u < 4; u++) {
            int s = t + 256 * u;
            float v = ss[s];
            if (v > bv || (v == bv && s < bi)) { bv = v; bi = s; }
        }
        red[t] = bv; redi[t] = bi;
        __syncthreads();
        for (int off = 128; off > 0; off >>= 1) {
            if (t < off) {
                float v2 = red[t + off]; int i2 = redi[t + off];
                if (v2 > red[t] || (v2 == red[t] && i2 < redi[t])) { red[t] = v2; redi[t] = i2; }
            }
            __syncthreads();
        }
        if (t == 0) { idxs[it] = redi[0]; ss[redi[0]] = -INFINITY; }
        __syncthreads();
    }

    for (int e = t; e < KSEL * DS; e += 256) {
        int j = e >> 6, d = e & 63;
        out_sel[((size_t)b * KSEL + j) * DS + d] = Hb[(size_t)idxs[j] * DS + d];
    }
}

// ============================================================================
extern "C" void kernel_launch(void* const* d_in, const int* in_sizes, int n_in,
                              void* d_out, int out_size) {
    const float* X    = (const float*)d_in[0];
    const float* mask = (const float*)d_in[1];
    const float* W1   = (const float*)d_in[2];
    const float* b1   = (const float*)d_in[3];
    const float* W2   = (const float*)d_in[4];
    const float* b2   = (const float*)d_in[5];
    const float* q    = (const float*)d_in[6];

    float* out      = (float*)d_out;
    float* out_sel  = out;
    float* out_ctx  = out + (size_t)NB * KSEL * DS;
    float* out_attn = out_ctx + (size_t)NB * DS;

    cudaFuncSetAttribute(k1_mlp, cudaFuncAttributeMaxDynamicSharedMemorySize, SM_TOTAL);

    // Split k1 into 3 launches (4 launches per call) so ncu's `-s 5 -c 1`
    // lands on a k1 chunk instead of always hitting k2.
    const int total = (NB * NS) / BM;          // 8192
    const int c1 = 2731, c2 = 2731, c3 = total - c1 - c2;
    k1_mlp<<<c1, 256, SM_TOTAL>>>(X, W1, b1, W2, b2, q, 0);
    k1_mlp<<<c2, 256, SM_TOTAL>>>(X, W1, b1, W2, b2, q, c1);
    k1_mlp<<<c3, 256, SM_TOTAL>>>(X, W1, b1, W2, b2, q, c1 + c2);
    k2_attn<<<NB, 256>>>(mask, out_sel, out_ctx, out_attn);
}

// round 5
// speedup vs baseline: 1.4586x; 1.4586x over previous
#include <cuda_runtime.h>
#include <math.h>

#define NB 1024
#define NS 1024
#define DI 128
#define DS 64
#define KSEL 8

typedef unsigned long long ull;

__device__ float g_H[(size_t)NB * NS * DS];       // 256 MB
__device__ float g_scores[(size_t)NB * NS];       // 4 MB

__device__ __forceinline__ ull fma2(ull a, ull b, ull c) {
    ull d;
    asm("fma.rn.f32x2 %0, %1, %2, %3;" : "=l"(d) : "l"(a), "l"(b), "l"(c));
    return d;
}
__device__ __forceinline__ float lo2(ull v) { return __uint_as_float((unsigned int)v); }
__device__ __forceinline__ float hi2(ull v) { return __uint_as_float((unsigned int)(v >> 32)); }
__device__ __forceinline__ ull pack2(float lo, float hi) {
    return (ull)__float_as_uint(lo) | ((ull)__float_as_uint(hi) << 32);
}

// ============================================================================
// K1: fused MLP + score. BM=128 rows/block, 256 threads, 8x4 outputs/thread.
// Row-pairs packed in f32x2 accumulators; weights stored DUPLICATED in smem
// as two parallel float4 arrays (Wa: cols {0,1} dup'd, Wb: cols {2,3} dup'd)
// so b-side LDS.128 is contiguous (conflict-free) and yields two broadcast
// f32x2 operands with zero MOVs.
// ============================================================================
static constexpr int BM = 128;
static constexpr int BK = 16;
static constexpr int XST = 130;   // padded row stride (even -> 8B-aligned pairs)

// dynamic smem layout (bytes):
//   region A [0, 33280):
//     GEMM1 phase: XsT float[16][130] @ 0 (8320), W1a float4[16][16] @ 8320
//                  (4096), W1b float4[16][16] @ 12416 (4096)
//     GEMM2 phase: TsT float[64][130] @ 0 (33280) overlays all of the above
//   W2a float4[64][16] @ 33280 (16384)
//   W2b float4[64][16] @ 49664 (16384)
//   qms float[64]      @ 66048 (256)
static constexpr int SM_XST = 0;
static constexpr int SM_W1A = 8320;
static constexpr int SM_W1B = 12416;
static constexpr int SM_TST = 0;
static constexpr int SM_W2A = 33280;
static constexpr int SM_W2B = 49664;
static constexpr int SM_QMS = 66048;
static constexpr int SM_TOTAL = 66304;

__global__ __launch_bounds__(256, 2) void k1_mlp(
    const float* __restrict__ X, const float* __restrict__ W1,
    const float* __restrict__ b1, const float* __restrict__ W2,
    const float* __restrict__ b2, const float* __restrict__ q)
{
    extern __shared__ __align__(16) char sm[];
    float  (*XsT)[XST] = (float (*)[XST])(sm + SM_XST);
    float4 (*W1a)[16]  = (float4(*)[16])(sm + SM_W1A);
    float4 (*W1b)[16]  = (float4(*)[16])(sm + SM_W1B);
    float  (*TsT)[XST] = (float (*)[XST])(sm + SM_TST);
    float4 (*W2a)[16]  = (float4(*)[16])(sm + SM_W2A);
    float4 (*W2b)[16]  = (float4(*)[16])(sm + SM_W2B);
    float* qms = (float*)(sm + SM_QMS);

    const int tid = threadIdx.x;
    const int tx = tid & 15;     // col group: cols tx*4 .. tx*4+3
    const int ty = tid >> 4;     // row group: rows ty*8 .. ty*8+7
    const size_t row0 = (size_t)blockIdx.x * BM;

    // ---- preload duplicated W2 (split arrays) + head-mean q ----
    #pragma unroll
    for (int u = 0; u < 4; u++) {
        int idx = tid + 256 * u;             // 1024 float4 of W2
        float4 w = ((const float4*)W2)[idx];
        int kk = idx >> 4, c4 = idx & 15;
        W2a[kk][c4] = make_float4(w.x, w.x, w.y, w.y);
        W2b[kk][c4] = make_float4(w.z, w.z, w.w, w.w);
    }
    if (tid < DS) qms[tid] = 0.5f * (q[tid] + q[DS + tid]);

    ull acc[4][4];   // [row-pair p][col c] ; rows ty*8+2p, ty*8+2p+1
    #pragma unroll
    for (int p = 0; p < 4; p++)
        #pragma unroll
        for (int c = 0; c < 4; c++) acc[p][c] = 0ULL;

    // loader mappings
    const int xr0 = tid >> 2;          // X rows (and +64)
    const int xc4 = tid & 3;           // X k-subgroup
    const int wkk = tid >> 4;          // W1 tile k row
    const int wc4 = tid & 15;          // W1 col group

    float4 xA, xB, wv;
    xA = *(const float4*)(X + (row0 + xr0) * DI + xc4 * 4);
    xB = *(const float4*)(X + (row0 + xr0 + 64) * DI + xc4 * 4);
    wv = *(const float4*)(W1 + (size_t)wkk * DS + wc4 * 4);

    // ---- GEMM1: T = relu(X @ W1 + b1), K=128 in 8 tiles of 16 ----
    for (int t = 0; t < 8; t++) {
        __syncthreads();
        XsT[xc4 * 4 + 0][xr0] = xA.x;  XsT[xc4 * 4 + 0][xr0 + 64] = xB.x;
        XsT[xc4 * 4 + 1][xr0] = xA.y;  XsT[xc4 * 4 + 1][xr0 + 64] = xB.y;
        XsT[xc4 * 4 + 2][xr0] = xA.z;  XsT[xc4 * 4 + 2][xr0 + 64] = xB.z;
        XsT[xc4 * 4 + 3][xr0] = xA.w;  XsT[xc4 * 4 + 3][xr0 + 64] = xB.w;
        W1a[wkk][wc4] = make_float4(wv.x, wv.x, wv.y, wv.y);
        W1b[wkk][wc4] = make_float4(wv.z, wv.z, wv.w, wv.w);
        __syncthreads();

        if (t < 7) {
            int k0 = (t + 1) * BK;
            xA = *(const float4*)(X + (row0 + xr0) * DI + k0 + xc4 * 4);
            xB = *(const float4*)(X + (row0 + xr0 + 64) * DI + k0 + xc4 * 4);
            wv = *(const float4*)(W1 + (size_t)(k0 + wkk) * DS + wc4 * 4);
        }

        #pragma unroll
        for (int kk = 0; kk < BK; kk++) {
            ull a[4];
            #pragma unroll
            for (int p = 0; p < 4; p++)
                a[p] = *(const ull*)&XsT[kk][ty * 8 + 2 * p];
            ulonglong2 bA = *(const ulonglong2*)&W1a[kk][tx];   // (w0,w0),(w1,w1)
            ulonglong2 bB = *(const ulonglong2*)&W1b[kk][tx];   // (w2,w2),(w3,w3)
            #pragma unroll
            for (int p = 0; p < 4; p++) {
                acc[p][0] = fma2(a[p], bA.x, acc[p][0]);
                acc[p][1] = fma2(a[p], bA.y, acc[p][1]);
                acc[p][2] = fma2(a[p], bB.x, acc[p][2]);
                acc[p][3] = fma2(a[p], bB.y, acc[p][3]);
            }
        }
    }

    // ---- bias + relu -> TsT (overlays XsT/W1 region; sync first) ----
    {
        float4 b1v = *(const float4*)(b1 + tx * 4);
        float bb[4] = {b1v.x, b1v.y, b1v.z, b1v.w};
        __syncthreads();   // everyone done reading XsT/W1a/W1b
        #pragma unroll
        for (int p = 0; p < 4; p++)
            #pragma unroll
            for (int c = 0; c < 4; c++) {
                float lo = fmaxf(lo2(acc[p][c]) + bb[c], 0.0f);
                float hi = fmaxf(hi2(acc[p][c]) + bb[c], 0.0f);
                *(ull*)&TsT[tx * 4 + c][ty * 8 + 2 * p] = pack2(lo, hi);
                acc[p][c] = 0ULL;
            }
    }
    __syncthreads();

    // ---- GEMM2: H = T @ W2 + b2, K = 64 ----
    #pragma unroll 16
    for (int kk = 0; kk < DS; kk++) {
        ull a[4];
        #pragma unroll
        for (int p = 0; p < 4; p++)
            a[p] = *(const ull*)&TsT[kk][ty * 8 + 2 * p];
        ulonglong2 bA = *(const ulonglong2*)&W2a[kk][tx];
        ulonglong2 bB = *(const ulonglong2*)&W2b[kk][tx];
        #pragma unroll
        for (int p = 0; p < 4; p++) {
            acc[p][0] = fma2(a[p], bA.x, acc[p][0]);
            acc[p][1] = fma2(a[p], bA.y, acc[p][1]);
            acc[p][2] = fma2(a[p], bB.x, acc[p][2]);
            acc[p][3] = fma2(a[p], bB.y, acc[p][3]);
        }
    }

    // ---- epilogue: bias, write H, per-row scores ----
    float4 b2v = *(const float4*)(b2 + tx * 4);
    float bb2[4] = {b2v.x, b2v.y, b2v.z, b2v.w};
    float q0 = qms[tx * 4 + 0], q1 = qms[tx * 4 + 1];
    float q2 = qms[tx * 4 + 2], q3 = qms[tx * 4 + 3];

    #pragma unroll
    for (int p = 0; p < 4; p++) {
        float hl[4], hh[4];
        #pragma unroll
        for (int c = 0; c < 4; c++) {
            hl[c] = lo2(acc[p][c]) + bb2[c];
            hh[c] = hi2(acc[p][c]) + bb2[c];
        }
        size_t re = row0 + ty * 8 + 2 * p;
        *(float4*)&g_H[re * DS + tx * 4]       = make_float4(hl[0], hl[1], hl[2], hl[3]);
        *(float4*)&g_H[(re + 1) * DS + tx * 4] = make_float4(hh[0], hh[1], hh[2], hh[3]);

        float ve = hl[0] * q0 + hl[1] * q1 + hl[2] * q2 + hl[3] * q3;
        float vo = hh[0] * q0 + hh[1] * q1 + hh[2] * q2 + hh[3] * q3;
        #pragma unroll
        for (int m = 8; m > 0; m >>= 1) {
            ve += __shfl_xor_sync(0xffffffffu, ve, m);
            vo += __shfl_xor_sync(0xffffffffu, vo, m);
        }
        if (tx == 0) {
            g_scores[re]     = ve * 0.125f;
            g_scores[re + 1] = vo * 0.125f;
        }
    }
}

// ============================================================================
// K2: per-batch masked softmax + ctx + top-8 + gather. One block per batch.
// ============================================================================
__global__ __launch_bounds__(256) void k2_attn(
    const float* __restrict__ mask,
    float* __restrict__ out_sel, float* __restrict__ out_ctx,
    float* __restrict__ out_attn)
{
    __shared__ float sms[NS];
    __shared__ float ss[NS];
    __shared__ float aw[NS];
    __shared__ float red[256];
    __shared__ int   redi[256];
    __shared__ float cpart[4][DS];
    __shared__ int   idxs[KSEL];

    const int t = threadIdx.x;
    const int b = blockIdx.x;
    const float* sc = g_scores + (size_t)b * NS;
    const float* mk = mask + (size_t)b * NS;

    float lmax = -INFINITY;
    #pragma unroll
    for (int u = 0; u < 4; u++) {
        int s = t + 256 * u;
        float v = sc[s];
        float m = (mk[s] > 0.5f) ? v : -INFINITY;
        sms[s] = m;
        lmax = fmaxf(lmax, m);
    }
    red[t] = lmax;
    __syncthreads();
    for (int off = 128; off > 0; off >>= 1) {
        if (t < off) red[t] = fmaxf(red[t], red[t + off]);
        __syncthreads();
    }
    const float mx = red[0];
    const bool allm = !(mx > -INFINITY);
    __syncthreads();

    float lsum = 0.0f;
    #pragma unroll
    for (int u = 0; u < 4; u++) {
        int s = t + 256 * u;
        float m = sms[s];
        float e;
        if (allm)                e = 1.0f;
        else if (m == -INFINITY) e = 0.0f;
        else                     e = expf(m - mx);
        aw[s] = e;
        lsum += e;
    }
    red[t] = lsum;
    __syncthreads();
    for (int off = 128; off > 0; off >>= 1) {
        if (t < off) red[t] += red[t + off];
        __syncthreads();
    }
    const float inv = 1.0f / red[0];
    __syncthreads();
    #pragma unroll
    for (int u = 0; u < 4; u++) {
        int s = t + 256 * u;
        float w = aw[s] * inv;
        aw[s] = w;
        out_attn[(size_t)b * NS + s] = w;
        ss[s] = allm ? 0.0f : sms[s];
    }
    __syncthreads();

    const float* Hb = g_H + (size_t)b * NS * DS;
    {
        const int d = t & 63, part = t >> 6;
        float acc = 0.0f;
        const int s0 = part * 256;
        #pragma unroll 8
        for (int s = s0; s < s0 + 256; s++)
            acc += aw[s] * Hb[(size_t)s * DS + d];
        cpart[part][d] = acc;
    }
    __syncthreads();
    if (t < DS)
        out_ctx[(size_t)b * DS + t] =
            (cpart[0][t] + cpart[1][t]) + (cpart[2][t] + cpart[3][t]);

    for (int it = 0; it < KSEL; it++) {
        float bv = -INFINITY; int bi = 0x7fffffff;
        #pragma unroll
        for (int u = 0; u < 4; u++) {
            int s = t + 256 * u;
            float v = ss[s];
            if (v > bv || (v == bv && s < bi)) { bv = v; bi = s; }
        }
        red[t] = bv; redi[t] = bi;
        __syncthreads();
        for (int off = 128; off > 0; off >>= 1) {
            if (t < off) {
                float v2 = red[t + off]; int i2 = redi[t + off];
                if (v2 > red[t] || (v2 == red[t] && i2 < redi[t])) { red[t] = v2; redi[t] = i2; }
            }
            __syncthreads();
        }
        if (t == 0) { idxs[it] = redi[0]; ss[redi[0]] = -INFINITY; }
        __syncthreads();
    }

    for (int e = t; e < KSEL * DS; e += 256) {
        int j = e >> 6, d = e & 63;
        out_sel[((size_t)b * KSEL + j) * DS + d] = Hb[(size_t)idxs[j] * DS + d];
    }
}

// ============================================================================
extern "C" void kernel_launch(void* const* d_in, const int* in_sizes, int n_in,
                              void* d_out, int out_size) {
    const float* X    = (const float*)d_in[0];
    const float* mask = (const float*)d_in[1];
    const float* W1   = (const float*)d_in[2];
    const float* b1   = (const float*)d_in[3];
    const float* W2   = (const float*)d_in[4];
    const float* b2   = (const float*)d_in[5];
    const float* q    = (const float*)d_in[6];

    float* out      = (float*)d_out;
    float* out_sel  = out;
    float* out_ctx  = out + (size_t)NB * KSEL * DS;
    float* out_attn = out_ctx + (size_t)NB * DS;

    cudaFuncSetAttribute(k1_mlp, cudaFuncAttributeMaxDynamicSharedMemorySize, SM_TOTAL);

    k1_mlp<<<(NB * NS) / BM, 256, SM_TOTAL>>>(X, W1, b1, W2, b2, q);
    k2_attn<<<NB, 256>>>(mask, out_sel, out_ctx, out_attn);
}

// round 9
// speedup vs baseline: 1.9347x; 1.3264x over previous
#include <cuda_runtime.h>
#include <cuda_bf16.h>
#include <stdint.h>
#include <math.h>

#define NB 1024
#define NS 1024
#define DI 128
#define DS 64
#define KSEL 8

typedef unsigned long long ull;

__device__ float g_H[(size_t)NB * NS * DS];       // 256 MB
__device__ float g_scores[(size_t)NB * NS];       // 4 MB

// ======================= helpers =======================
__device__ __forceinline__ uint32_t smem_u32(const void* p) {
    uint32_t a;
    asm("{ .reg .u64 t; cvta.to.shared.u64 t, %1; cvt.u32.u64 %0, t; }" : "=r"(a) : "l"(p));
    return a;
}
// 2-way split: fp32 pair -> packed bf16x2 (hi, lo residual)
__device__ __forceinline__ void split2(float a, float b, uint32_t& hi, uint32_t& lo) {
    __nv_bfloat162 h = __float22bfloat162_rn(make_float2(a, b));
    float2 hf = __bfloat1622float2(h);
    __nv_bfloat162 l = __float22bfloat162_rn(make_float2(a - hf.x, b - hf.y));
    hi = *reinterpret_cast<uint32_t*>(&h);
    lo = *reinterpret_cast<uint32_t*>(&l);
}
// 3-way split: fp32 pair -> packed bf16x2 (hi, mid, lo) ; residual ~2^-26
__device__ __forceinline__ void split3(float a, float b, uint32_t& h, uint32_t& m, uint32_t& l) {
    __nv_bfloat162 H = __float22bfloat162_rn(make_float2(a, b));
    float2 Hf = __bfloat1622float2(H);
    float ra = a - Hf.x, rb = b - Hf.y;
    __nv_bfloat162 M = __float22bfloat162_rn(make_float2(ra, rb));
    float2 Mf = __bfloat1622float2(M);
    __nv_bfloat162 L = __float22bfloat162_rn(make_float2(ra - Mf.x, rb - Mf.y));
    h = *reinterpret_cast<uint32_t*>(&H);
    m = *reinterpret_cast<uint32_t*>(&M);
    l = *reinterpret_cast<uint32_t*>(&L);
}
__device__ __forceinline__ void ldm4(uint32_t r[4], uint32_t addr) {
    asm volatile("ldmatrix.sync.aligned.m8n8.x4.shared.b16 {%0,%1,%2,%3}, [%4];"
        : "=r"(r[0]), "=r"(r[1]), "=r"(r[2]), "=r"(r[3]) : "r"(addr));
}
__device__ __forceinline__ void mma16816(float c[4], const uint32_t a[4],
                                         uint32_t b0, uint32_t b1) {
    asm volatile(
        "mma.sync.aligned.m16n8k16.row.col.f32.bf16.bf16.f32 "
        "{%0,%1,%2,%3}, {%4,%5,%6,%7}, {%8,%9}, {%0,%1,%2,%3};"
        : "+f"(c[0]), "+f"(c[1]), "+f"(c[2]), "+f"(c[3])
        : "r"(a[0]), "r"(a[1]), "r"(a[2]), "r"(a[3]), "r"(b0), "r"(b1));
}

// ======================= K1: split-bf16 HMMA MLP =======================
// smem (bytes):
//  XH @0      (16K) [128 r][64 k] bf16, 128B rows, chunk swizzle c^(r&7)
//  XM @16384  (16K)   (phase2: TH/TL overlay XH/XM)
//  XL @32768  (16K)
//  W1H/W1M/W1L @49152/57344/65536 (8K each) [64 n][64 k] per K-pass
//  W2H/W2L @73728/81920 (8K each) [64 n][64 k]
//  WT @90112 (w~ = W2*qm, 64 f + b2qm @ idx 64 -> 272B pad 272)
//  B1S @90384 (256), B2S @90640 (256) -> total 90896
static constexpr int SM_XH = 0,      SM_XM = 16384, SM_XL = 32768;
static constexpr int SM_W1H = 49152, SM_W1M = 57344, SM_W1L = 65536;
static constexpr int SM_W2H = 73728, SM_W2L = 81920;
static constexpr int SM_WT = 90112,  SM_B1S = 90384, SM_B2S = 90640;
static constexpr int SM_TOTAL = 90896;

__global__ __launch_bounds__(256, 2) void k1_mlp(
    const float* __restrict__ X,  const float* __restrict__ W1,
    const float* __restrict__ b1, const float* __restrict__ W2,
    const float* __restrict__ b2, const float* __restrict__ q)
{
    extern __shared__ __align__(16) char sm[];
    const uint32_t sb = smem_u32(sm);
    float* wt  = (float*)(sm + SM_WT);
    float* b1s = (float*)(sm + SM_B1S);
    float* b2s = (float*)(sm + SM_B2S);

    const int tid  = threadIdx.x;
    const int warp = tid >> 5, lane = tid & 31;
    const int grp  = lane >> 2, qd = lane & 3;
    const int warpR = warp * 16;
    const size_t row0 = (size_t)blockIdx.x * 128;

    // ---- preamble: biases, w~ = W2*qm (fp32), b2qm ----
    if (tid < DS) {
        b1s[tid] = b1[tid];
        b2s[tid] = b2[tid];
        float acc = 0.0f;
        #pragma unroll 8
        for (int d = 0; d < DS; d++)
            acc += W2[(size_t)tid * DS + d] * (0.5f * (q[d] + q[DS + d]));
        wt[tid] = acc;
    } else if (tid == 64) {
        float acc = 0.0f;
        #pragma unroll 8
        for (int d = 0; d < DS; d++)
            acc += b2[d] * (0.5f * (q[d] + q[DS + d]));
        wt[64] = acc;   // b2 . qm
    }
    // ---- W2 -> [n][k] 2-way split tiles ----
    #pragma unroll
    for (int i = 0; i < 2; i++) {
        int task = tid + 256 * i;           // 512 tasks: (n, kc) kc 0..7
        int n = task & 63, kc = task >> 6;
        uint32_t h[4], l[4];
        #pragma unroll
        for (int j = 0; j < 4; j++) {
            float v0 = W2[(size_t)(kc * 8 + j * 2 + 0) * DS + n];
            float v1 = W2[(size_t)(kc * 8 + j * 2 + 1) * DS + n];
            split2(v0, v1, h[j], l[j]);
        }
        uint32_t off = (uint32_t)n * 128 + (uint32_t)((kc ^ (n & 7)) << 4);
        *(uint4*)(sm + SM_W2H + off) = make_uint4(h[0], h[1], h[2], h[3]);
        *(uint4*)(sm + SM_W2L + off) = make_uint4(l[0], l[1], l[2], l[3]);
    }

    float c1[8][4];
    #pragma unroll
    for (int nt = 0; nt < 8; nt++)
        #pragma unroll
        for (int j = 0; j < 4; j++) c1[nt][j] = 0.0f;

    // ================= GEMM1: two K=64 passes, 3-way split (6 MMA) =================
    for (int p = 0; p < 2; p++) {
        // stage global loads in registers
        float4 xa[4], xb[4];
        #pragma unroll
        for (int i = 0; i < 4; i++) {
            int task = tid + 256 * i;       // (r, c): 128 rows x 8 chunks
            int r = task >> 3, c = task & 7;
            const float* src = X + (row0 + r) * DI + p * 64 + c * 8;
            xa[i] = *(const float4*)src;
            xb[i] = *(const float4*)(src + 4);
        }
        float w1v[2][8];
        #pragma unroll
        for (int i = 0; i < 2; i++) {
            int task = tid + 256 * i;       // (n, kc): 64 x 8
            int n = task & 63, kc = task >> 6;
            #pragma unroll
            for (int j = 0; j < 8; j++)
                w1v[i][j] = W1[(size_t)(p * 64 + kc * 8 + j) * DS + n];
        }
        __syncthreads();    // prior smem reads complete
        #pragma unroll
        for (int i = 0; i < 4; i++) {
            int task = tid + 256 * i;
            int r = task >> 3, c = task & 7;
            uint32_t h[4], m[4], l[4];
            split3(xa[i].x, xa[i].y, h[0], m[0], l[0]);
            split3(xa[i].z, xa[i].w, h[1], m[1], l[1]);
            split3(xb[i].x, xb[i].y, h[2], m[2], l[2]);
            split3(xb[i].z, xb[i].w, h[3], m[3], l[3]);
            uint32_t off = (uint32_t)r * 128 + (uint32_t)((c ^ (r & 7)) << 4);
            *(uint4*)(sm + SM_XH + off) = make_uint4(h[0], h[1], h[2], h[3]);
            *(uint4*)(sm + SM_XM + off) = make_uint4(m[0], m[1], m[2], m[3]);
            *(uint4*)(sm + SM_XL + off) = make_uint4(l[0], l[1], l[2], l[3]);
        }
        #pragma unroll
        for (int i = 0; i < 2; i++) {
            int task = tid + 256 * i;
            int n = task & 63, kc = task >> 6;
            uint32_t h[4], m[4], l[4];
            #pragma unroll
            for (int j = 0; j < 4; j++)
                split3(w1v[i][j * 2], w1v[i][j * 2 + 1], h[j], m[j], l[j]);
            uint32_t off = (uint32_t)n * 128 + (uint32_t)((kc ^ (n & 7)) << 4);
            *(uint4*)(sm + SM_W1H + off) = make_uint4(h[0], h[1], h[2], h[3]);
            *(uint4*)(sm + SM_W1M + off) = make_uint4(m[0], m[1], m[2], m[3]);
            *(uint4*)(sm + SM_W1L + off) = make_uint4(l[0], l[1], l[2], l[3]);
        }
        __syncthreads();

        #pragma unroll
        for (int ks = 0; ks < 4; ks++) {
            uint32_t ah[4], am[4], al[4];
            {
                int seg = lane >> 3, ri = lane & 7;
                int r = warpR + (seg & 1) * 8 + ri;
                int c = 2 * ks + (seg >> 1);
                uint32_t off = (uint32_t)r * 128 + (uint32_t)((c ^ (r & 7)) << 4);
                ldm4(ah, sb + SM_XH + off);
                ldm4(am, sb + SM_XM + off);
                ldm4(al, sb + SM_XL + off);
            }
            uint32_t bh[16], bm[16], bl[16];
            #pragma unroll
            for (int g = 0; g < 4; g++) {
                int seg = lane >> 3, ri = lane & 7;
                int n = (g * 2 + (seg >> 1)) * 8 + ri;
                int c = 2 * ks + (seg & 1);
                uint32_t off = (uint32_t)n * 128 + (uint32_t)((c ^ (n & 7)) << 4);
                ldm4(&bh[g * 4], sb + SM_W1H + off);
                ldm4(&bm[g * 4], sb + SM_W1M + off);
                ldm4(&bl[g * 4], sb + SM_W1L + off);
            }
            #pragma unroll
            for (int nt = 0; nt < 8; nt++) {
                uint32_t b0h = bh[nt * 2], b1h = bh[nt * 2 + 1];
                uint32_t b0m = bm[nt * 2], b1m = bm[nt * 2 + 1];
                uint32_t b0l = bl[nt * 2], b1l = bl[nt * 2 + 1];
                mma16816(c1[nt], ah, b0h, b1h);   // hh
                mma16816(c1[nt], ah, b0m, b1m);   // hm
                mma16816(c1[nt], am, b0h, b1h);   // mh
                mma16816(c1[nt], am, b0m, b1m);   // mm
                mma16816(c1[nt], ah, b0l, b1l);   // hl
                mma16816(c1[nt], al, b0h, b1h);   // lh
            }
        }
    }
    __syncthreads();    // all GEMM1 smem reads done; XH/XM become TH/TL

    // ---- relu + b1 -> fp32 score (w~) + 2-way split -> T ----
    const int rA = warpR + grp, rB = rA + 8;
    {
        float pA = 0.0f, pB = 0.0f;
        #pragma unroll
        for (int nt = 0; nt < 8; nt++) {
            int c0 = nt * 8 + qd * 2;
            float t0 = fmaxf(c1[nt][0] + b1s[c0],     0.0f);
            float t1 = fmaxf(c1[nt][1] + b1s[c0 + 1], 0.0f);
            float t2 = fmaxf(c1[nt][2] + b1s[c0],     0.0f);
            float t3 = fmaxf(c1[nt][3] + b1s[c0 + 1], 0.0f);
            pA += t0 * wt[c0] + t1 * wt[c0 + 1];
            pB += t2 * wt[c0] + t3 * wt[c0 + 1];
            uint32_t h01, l01, h23, l23;
            split2(t0, t1, h01, l01);
            split2(t2, t3, h23, l23);
            uint32_t offA = (uint32_t)rA * 128 + (uint32_t)((nt ^ (rA & 7)) << 4) + qd * 4;
            uint32_t offB = (uint32_t)rB * 128 + (uint32_t)((nt ^ (rB & 7)) << 4) + qd * 4;
            *(uint32_t*)(sm + SM_XH + offA) = h01;
            *(uint32_t*)(sm + SM_XM + offA) = l01;
            *(uint32_t*)(sm + SM_XH + offB) = h23;
            *(uint32_t*)(sm + SM_XM + offB) = l23;
        }
        pA += __shfl_xor_sync(0xffffffffu, pA, 1);
        pA += __shfl_xor_sync(0xffffffffu, pA, 2);
        pB += __shfl_xor_sync(0xffffffffu, pB, 1);
        pB += __shfl_xor_sync(0xffffffffu, pB, 2);
        if (qd == 0) {
            float b2qm = wt[64];
            g_scores[row0 + rA] = (pA + b2qm) * 0.125f;
            g_scores[row0 + rB] = (pB + b2qm) * 0.125f;
        }
    }
    __syncthreads();

    // ================= GEMM2: H = T @ W2 + b2 (K=64, 3-term) =================
    float c2[8][4];
    #pragma unroll
    for (int nt = 0; nt < 8; nt++)
        #pragma unroll
        for (int j = 0; j < 4; j++) c2[nt][j] = 0.0f;

    #pragma unroll
    for (int ks = 0; ks < 4; ks++) {
        uint32_t ah[4], al[4];
        {
            int seg = lane >> 3, ri = lane & 7;
            int r = warpR + (seg & 1) * 8 + ri;
            int c = 2 * ks + (seg >> 1);
            uint32_t off = (uint32_t)r * 128 + (uint32_t)((c ^ (r & 7)) << 4);
            ldm4(ah, sb + SM_XH + off);   // THI
            ldm4(al, sb + SM_XM + off);   // TLO
        }
        uint32_t bh[16], bl[16];
        #pragma unroll
        for (int g = 0; g < 4; g++) {
            int seg = lane >> 3, ri = lane & 7;
            int n = (g * 2 + (seg >> 1)) * 8 + ri;
            int c = 2 * ks + (seg & 1);
            uint32_t off = (uint32_t)n * 128 + (uint32_t)((c ^ (n & 7)) << 4);
            ldm4(&bh[g * 4], sb + SM_W2H + off);
            ldm4(&bl[g * 4], sb + SM_W2L + off);
        }
        #pragma unroll
        for (int nt = 0; nt < 8; nt++) {
            mma16816(c2[nt], ah, bh[nt * 2], bh[nt * 2 + 1]);
            mma16816(c2[nt], ah, bl[nt * 2], bl[nt * 2 + 1]);
            mma16816(c2[nt], al, bh[nt * 2], bh[nt * 2 + 1]);
        }
    }

    // ---- epilogue: +b2, direct H store (32B sectors) ----
    #pragma unroll
    for (int nt = 0; nt < 8; nt++) {
        int c0 = nt * 8 + qd * 2;
        float hA0 = c2[nt][0] + b2s[c0], hA1 = c2[nt][1] + b2s[c0 + 1];
        float hB0 = c2[nt][2] + b2s[c0], hB1 = c2[nt][3] + b2s[c0 + 1];
        *(float2*)&g_H[(row0 + rA) * DS + c0] = make_float2(hA0, hA1);
        *(float2*)&g_H[(row0 + rB) * DS + c0] = make_float2(hB0, hB1);
    }
}

// ======================= K2 (unchanged, passing) =======================
__global__ __launch_bounds__(256) void k2_attn(
    const float* __restrict__ mask,
    float* __restrict__ out_sel, float* __restrict__ out_ctx,
    float* __restrict__ out_attn)
{
    __shared__ float sms[NS];
    __shared__ float ss[NS];
    __shared__ float aw[NS];
    __shared__ float red[256];
    __shared__ int   redi[256];
    __shared__ float cpart[4][DS];
    __shared__ int   idxs[KSEL];

    const int t = threadIdx.x;
    const int b = blockIdx.x;
    const float* sc = g_scores + (size_t)b * NS;
    const float* mk = mask + (size_t)b * NS;

    float lmax = -INFINITY;
    #pragma unroll
    for (int u = 0; u < 4; u++) {
        int s = t + 256 * u;
        float v = sc[s];
        float m = (mk[s] > 0.5f) ? v : -INFINITY;
        sms[s] = m;
        lmax = fmaxf(lmax, m);
    }
    red[t] = lmax;
    __syncthreads();
    for (int off = 128; off > 0; off >>= 1) {
        if (t < off) red[t] = fmaxf(red[t], red[t + off]);
        __syncthreads();
    }
    const float mx = red[0];
    const bool allm = !(mx > -INFINITY);
    __syncthreads();

    float lsum = 0.0f;
    #pragma unroll
    for (int u = 0; u < 4; u++) {
        int s = t + 256 * u;
        float m = sms[s];
        float e;
        if (allm)                e = 1.0f;
        else if (m == -INFINITY) e = 0.0f;
        else                     e = expf(m - mx);
        aw[s] = e;
        lsum += e;
    }
    red[t] = lsum;
    __syncthreads();
    for (int off = 128; off > 0; off >>= 1) {
        if (t < off) red[t] += red[t + off];
        __syncthreads();
    }
    const float inv = 1.0f / red[0];
    __syncthreads();
    #pragma unroll
    for (int u = 0; u < 4; u++) {
        int s = t + 256 * u;
        float w = aw[s] * inv;
        aw[s] = w;
        out_attn[(size_t)b * NS + s] = w;
        ss[s] = allm ? 0.0f : sms[s];
    }
    __syncthreads();

    const float* Hb = g_H + (size_t)b * NS * DS;
    {
        const int d = t & 63, part = t >> 6;
        float acc = 0.0f;
        const int s0 = part * 256;
        #pragma unroll 8
        for (int s = s0; s < s0 + 256; s++)
            acc += aw[s] * Hb[(size_t)s * DS + d];
        cpart[part][d] = acc;
    }
    __syncthreads();
    if (t < DS)
        out_ctx[(size_t)b * DS + t] =
            (cpart[0][t] + cpart[1][t]) + (cpart[2][t] + cpart[3][t]);

    for (int it = 0; it < KSEL; it++) {
        float bv = -INFINITY; int bi = 0x7fffffff;
        #pragma unroll
        for (int u = 0; u < 4; u++) {
            int s = t + 256 * u;
            float v = ss[s];
            if (v > bv || (v == bv && s < bi)) { bv = v; bi = s; }
        }
        red[t] = bv; redi[t] = bi;
        __syncthreads();
        for (int off = 128; off > 0; off >>= 1) {
            if (t < off) {
                float v2 = red[t + off]; int i2 = redi[t + off];
                if (v2 > red[t] || (v2 == red[t] && i2 < redi[t])) { red[t] = v2; redi[t] = i2; }
            }
            __syncthreads();
        }
        if (t == 0) { idxs[it] = redi[0]; ss[redi[0]] = -INFINITY; }
        __syncthreads();
    }

    for (int e = t; e < KSEL * DS; e += 256) {
        int j = e >> 6, d = e & 63;
        out_sel[((size_t)b * KSEL + j) * DS + d] = Hb[(size_t)idxs[j] * DS + d];
    }
}

// ============================================================================
extern "C" void kernel_launch(void* const* d_in, const int* in_sizes, int n_in,
                              void* d_out, int out_size) {
    const float* X    = (const float*)d_in[0];
    const float* mask = (const float*)d_in[1];
    const float* W1   = (const float*)d_in[2];
    const float* b1   = (const float*)d_in[3];
    const float* W2   = (const float*)d_in[4];
    const float* b2   = (const float*)d_in[5];
    const float* q    = (const float*)d_in[6];

    float* out      = (float*)d_out;
    float* out_sel  = out;
    float* out_ctx  = out + (size_t)NB * KSEL * DS;
    float* out_attn = out_ctx + (size_t)NB * DS;

    cudaFuncSetAttribute(k1_mlp, cudaFuncAttributeMaxDynamicSharedMemorySize, SM_TOTAL);

    k1_mlp<<<(NB * NS) / 128, 256, SM_TOTAL>>>(X, W1, b1, W2, b2, q);
    k2_attn<<<NB, 256>>>(mask, out_sel, out_ctx, out_attn);
}

// round 10
// speedup vs baseline: 1.9411x; 1.0033x over previous
#include <cuda_runtime.h>
#include <cuda_bf16.h>
#include <stdint.h>
#include <math.h>

#define NB 1024
#define NS 1024
#define DI 128
#define DS 64
#define KSEL 8

typedef unsigned long long ull;

__device__ float g_H[(size_t)NB * NS * DS];       // 256 MB
__device__ float g_scores[(size_t)NB * NS];       // 4 MB

// ======================= helpers =======================
__device__ __forceinline__ uint32_t smem_u32(const void* p) {
    uint32_t a;
    asm("{ .reg .u64 t; cvta.to.shared.u64 t, %1; cvt.u32.u64 %0, t; }" : "=r"(a) : "l"(p));
    return a;
}
// 2-way split: fp32 pair -> packed bf16x2 (hi, lo residual)
__device__ __forceinline__ void split2(float a, float b, uint32_t& hi, uint32_t& lo) {
    __nv_bfloat162 h = __float22bfloat162_rn(make_float2(a, b));
    float2 hf = __bfloat1622float2(h);
    __nv_bfloat162 l = __float22bfloat162_rn(make_float2(a - hf.x, b - hf.y));
    hi = *reinterpret_cast<uint32_t*>(&h);
    lo = *reinterpret_cast<uint32_t*>(&l);
}
// 3-way split: fp32 pair -> packed bf16x2 (hi, mid, lo) ; residual ~2^-26
__device__ __forceinline__ void split3(float a, float b, uint32_t& h, uint32_t& m, uint32_t& l) {
    __nv_bfloat162 H = __float22bfloat162_rn(make_float2(a, b));
    float2 Hf = __bfloat1622float2(H);
    float ra = a - Hf.x, rb = b - Hf.y;
    __nv_bfloat162 M = __float22bfloat162_rn(make_float2(ra, rb));
    float2 Mf = __bfloat1622float2(M);
    __nv_bfloat162 L = __float22bfloat162_rn(make_float2(ra - Mf.x, rb - Mf.y));
    h = *reinterpret_cast<uint32_t*>(&H);
    m = *reinterpret_cast<uint32_t*>(&M);
    l = *reinterpret_cast<uint32_t*>(&L);
}
__device__ __forceinline__ void ldm4(uint32_t r[4], uint32_t addr) {
    asm volatile("ldmatrix.sync.aligned.m8n8.x4.shared.b16 {%0,%1,%2,%3}, [%4];"
        : "=r"(r[0]), "=r"(r[1]), "=r"(r[2]), "=r"(r[3]) : "r"(addr));
}
__device__ __forceinline__ void mma16816(float c[4], const uint32_t a[4],
                                         uint32_t b0, uint32_t b1) {
    asm volatile(
        "mma.sync.aligned.m16n8k16.row.col.f32.bf16.bf16.f32 "
        "{%0,%1,%2,%3}, {%4,%5,%6,%7}, {%8,%9}, {%0,%1,%2,%3};"
        : "+f"(c[0]), "+f"(c[1]), "+f"(c[2]), "+f"(c[3])
        : "r"(a[0]), "r"(a[1]), "r"(a[2]), "r"(a[3]), "r"(b0), "r"(b1));
}

// ======================= K1: split-bf16 HMMA MLP =======================
// smem layout identical to R9 (passing)
static constexpr int SM_XH = 0,      SM_XM = 16384, SM_XL = 32768;
static constexpr int SM_W1H = 49152, SM_W1M = 57344, SM_W1L = 65536;
static constexpr int SM_W2H = 73728, SM_W2L = 81920;
static constexpr int SM_WT = 90112,  SM_B1S = 90384, SM_B2S = 90640;
static constexpr int SM_TOTAL = 90896;

__global__ __launch_bounds__(256, 2) void k1_mlp(
    const float* __restrict__ X,  const float* __restrict__ W1,
    const float* __restrict__ b1, const float* __restrict__ W2,
    const float* __restrict__ b2, const float* __restrict__ q)
{
    extern __shared__ __align__(16) char sm[];
    const uint32_t sb = smem_u32(sm);
    float* wt  = (float*)(sm + SM_WT);
    float* b1s = (float*)(sm + SM_B1S);
    float* b2s = (float*)(sm + SM_B2S);

    const int tid  = threadIdx.x;
    const int warp = tid >> 5, lane = tid & 31;
    const int grp  = lane >> 2, qd = lane & 3;
    const int warpR = warp * 16;
    const size_t row0 = (size_t)blockIdx.x * 128;

    // ---- preamble: biases, w~ = W2*qm (fp32), b2.qm ----
    if (tid < DS) {
        b1s[tid] = b1[tid];
        b2s[tid] = b2[tid];
        float acc = 0.0f;
        #pragma unroll 8
        for (int d = 0; d < DS; d++)
            acc += W2[(size_t)tid * DS + d] * (0.5f * (q[d] + q[DS + d]));
        wt[tid] = acc;
    } else if (tid == 64) {
        float acc = 0.0f;
        #pragma unroll 8
        for (int d = 0; d < DS; d++)
            acc += b2[d] * (0.5f * (q[d] + q[DS + d]));
        wt[64] = acc;
    }
    // ---- W2 -> [n][k] 2-way split tiles ----
    #pragma unroll
    for (int i = 0; i < 2; i++) {
        int task = tid + 256 * i;
        int n = task & 63, kc = task >> 6;
        uint32_t h[4], l[4];
        #pragma unroll
        for (int j = 0; j < 4; j++) {
            float v0 = W2[(size_t)(kc * 8 + j * 2 + 0) * DS + n];
            float v1 = W2[(size_t)(kc * 8 + j * 2 + 1) * DS + n];
            split2(v0, v1, h[j], l[j]);
        }
        uint32_t off = (uint32_t)n * 128 + (uint32_t)((kc ^ (n & 7)) << 4);
        *(uint4*)(sm + SM_W2H + off) = make_uint4(h[0], h[1], h[2], h[3]);
        *(uint4*)(sm + SM_W2L + off) = make_uint4(l[0], l[1], l[2], l[3]);
    }

    float c1[8][4];
    #pragma unroll
    for (int nt = 0; nt < 8; nt++)
        #pragma unroll
        for (int j = 0; j < 4; j++) c1[nt][j] = 0.0f;

    // ================= GEMM1: two K=64 passes, 3-way split (6 terms) =================
    for (int p = 0; p < 2; p++) {
        float4 xa[4], xb[4];
        #pragma unroll
        for (int i = 0; i < 4; i++) {
            int task = tid + 256 * i;
            int r = task >> 3, c = task & 7;
            const float* src = X + (row0 + r) * DI + p * 64 + c * 8;
            xa[i] = *(const float4*)src;
            xb[i] = *(const float4*)(src + 4);
        }
        float w1v[2][8];
        #pragma unroll
        for (int i = 0; i < 2; i++) {
            int task = tid + 256 * i;
            int n = task & 63, kc = task >> 6;
            #pragma unroll
            for (int j = 0; j < 8; j++)
                w1v[i][j] = W1[(size_t)(p * 64 + kc * 8 + j) * DS + n];
        }
        __syncthreads();
        #pragma unroll
        for (int i = 0; i < 4; i++) {
            int task = tid + 256 * i;
            int r = task >> 3, c = task & 7;
            uint32_t h[4], m[4], l[4];
            split3(xa[i].x, xa[i].y, h[0], m[0], l[0]);
            split3(xa[i].z, xa[i].w, h[1], m[1], l[1]);
            split3(xb[i].x, xb[i].y, h[2], m[2], l[2]);
            split3(xb[i].z, xb[i].w, h[3], m[3], l[3]);
            uint32_t off = (uint32_t)r * 128 + (uint32_t)((c ^ (r & 7)) << 4);
            *(uint4*)(sm + SM_XH + off) = make_uint4(h[0], h[1], h[2], h[3]);
            *(uint4*)(sm + SM_XM + off) = make_uint4(m[0], m[1], m[2], m[3]);
            *(uint4*)(sm + SM_XL + off) = make_uint4(l[0], l[1], l[2], l[3]);
        }
        #pragma unroll
        for (int i = 0; i < 2; i++) {
            int task = tid + 256 * i;
            int n = task & 63, kc = task >> 6;
            uint32_t h[4], m[4], l[4];
            #pragma unroll
            for (int j = 0; j < 4; j++)
                split3(w1v[i][j * 2], w1v[i][j * 2 + 1], h[j], m[j], l[j]);
            uint32_t off = (uint32_t)n * 128 + (uint32_t)((kc ^ (n & 7)) << 4);
            *(uint4*)(sm + SM_W1H + off) = make_uint4(h[0], h[1], h[2], h[3]);
            *(uint4*)(sm + SM_W1M + off) = make_uint4(m[0], m[1], m[2], m[3]);
            *(uint4*)(sm + SM_W1L + off) = make_uint4(l[0], l[1], l[2], l[3]);
        }
        __syncthreads();

        #pragma unroll
        for (int ks = 0; ks < 4; ks++) {
            uint32_t ah[4], am[4], al[4];
            {
                int seg = lane >> 3, ri = lane & 7;
                int r = warpR + (seg & 1) * 8 + ri;
                int c = 2 * ks + (seg >> 1);
                uint32_t off = (uint32_t)r * 128 + (uint32_t)((c ^ (r & 7)) << 4);
                ldm4(ah, sb + SM_XH + off);
                ldm4(am, sb + SM_XM + off);
                ldm4(al, sb + SM_XL + off);
            }
            uint32_t bh[16], bm[16], bl[16];
            #pragma unroll
            for (int g = 0; g < 4; g++) {
                int seg = lane >> 3, ri = lane & 7;
                int n = (g * 2 + (seg >> 1)) * 8 + ri;
                int c = 2 * ks + (seg & 1);
                uint32_t off = (uint32_t)n * 128 + (uint32_t)((c ^ (n & 7)) << 4);
                ldm4(&bh[g * 4], sb + SM_W1H + off);
                ldm4(&bm[g * 4], sb + SM_W1M + off);
                ldm4(&bl[g * 4], sb + SM_W1L + off);
            }
            // term-major, nt-inner: consecutive MMAs hit DIFFERENT accumulators
            // (8 independent C frags between same-acc reuses -> RAW latency hidden).
            // Per-accumulator term order unchanged: hh, hm, mh, mm, hl, lh.
            #pragma unroll
            for (int nt = 0; nt < 8; nt++)   // hh
                mma16816(c1[nt], ah, bh[nt * 2], bh[nt * 2 + 1]);
            #pragma unroll
            for (int nt = 0; nt < 8; nt++)   // hm
                mma16816(c1[nt], ah, bm[nt * 2], bm[nt * 2 + 1]);
            #pragma unroll
            for (int nt = 0; nt < 8; nt++)   // mh
                mma16816(c1[nt], am, bh[nt * 2], bh[nt * 2 + 1]);
            #pragma unroll
            for (int nt = 0; nt < 8; nt++)   // mm
                mma16816(c1[nt], am, bm[nt * 2], bm[nt * 2 + 1]);
            #pragma unroll
            for (int nt = 0; nt < 8; nt++)   // hl
                mma16816(c1[nt], ah, bl[nt * 2], bl[nt * 2 + 1]);
            #pragma unroll
            for (int nt = 0; nt < 8; nt++)   // lh
                mma16816(c1[nt], al, bh[nt * 2], bh[nt * 2 + 1]);
        }
    }
    __syncthreads();    // GEMM1 smem reads done; XH/XM become TH/TL

    // ---- relu + b1 -> fp32 score (w~) + 2-way split -> T ----
    const int rA = warpR + grp, rB = rA + 8;
    {
        float pA = 0.0f, pB = 0.0f;
        #pragma unroll
        for (int nt = 0; nt < 8; nt++) {
            int c0 = nt * 8 + qd * 2;
            float t0 = fmaxf(c1[nt][0] + b1s[c0],     0.0f);
            float t1 = fmaxf(c1[nt][1] + b1s[c0 + 1], 0.0f);
            float t2 = fmaxf(c1[nt][2] + b1s[c0],     0.0f);
            float t3 = fmaxf(c1[nt][3] + b1s[c0 + 1], 0.0f);
            pA += t0 * wt[c0] + t1 * wt[c0 + 1];
            pB += t2 * wt[c0] + t3 * wt[c0 + 1];
            uint32_t h01, l01, h23, l23;
            split2(t0, t1, h01, l01);
            split2(t2, t3, h23, l23);
            uint32_t offA = (uint32_t)rA * 128 + (uint32_t)((nt ^ (rA & 7)) << 4) + qd * 4;
            uint32_t offB = (uint32_t)rB * 128 + (uint32_t)((nt ^ (rB & 7)) << 4) + qd * 4;
            *(uint32_t*)(sm + SM_XH + offA) = h01;
            *(uint32_t*)(sm + SM_XM + offA) = l01;
            *(uint32_t*)(sm + SM_XH + offB) = h23;
            *(uint32_t*)(sm + SM_XM + offB) = l23;
        }
        pA += __shfl_xor_sync(0xffffffffu, pA, 1);
        pA += __shfl_xor_sync(0xffffffffu, pA, 2);
        pB += __shfl_xor_sync(0xffffffffu, pB, 1);
        pB += __shfl_xor_sync(0xffffffffu, pB, 2);
        if (qd == 0) {
            float b2qm = wt[64];
            g_scores[row0 + rA] = (pA + b2qm) * 0.125f;
            g_scores[row0 + rB] = (pB + b2qm) * 0.125f;
        }
    }
    __syncthreads();

    // ================= GEMM2: H = T @ W2 + b2 (K=64, 3-term) =================
    float c2[8][4];
    #pragma unroll
    for (int nt = 0; nt < 8; nt++)
        #pragma unroll
        for (int j = 0; j < 4; j++) c2[nt][j] = 0.0f;

    #pragma unroll
    for (int ks = 0; ks < 4; ks++) {
        uint32_t ah[4], al[4];
        {
            int seg = lane >> 3, ri = lane & 7;
            int r = warpR + (seg & 1) * 8 + ri;
            int c = 2 * ks + (seg >> 1);
            uint32_t off = (uint32_t)r * 128 + (uint32_t)((c ^ (r & 7)) << 4);
            ldm4(ah, sb + SM_XH + off);   // THI
            ldm4(al, sb + SM_XM + off);   // TLO
        }
        uint32_t bh[16], bl[16];
        #pragma unroll
        for (int g = 0; g < 4; g++) {
            int seg = lane >> 3, ri = lane & 7;
            int n = (g * 2 + (seg >> 1)) * 8 + ri;
            int c = 2 * ks + (seg & 1);
            uint32_t off = (uint32_t)n * 128 + (uint32_t)((c ^ (n & 7)) << 4);
            ldm4(&bh[g * 4], sb + SM_W2H + off);
            ldm4(&bl[g * 4], sb + SM_W2L + off);
        }
        #pragma unroll
        for (int nt = 0; nt < 8; nt++)
            mma16816(c2[nt], ah, bh[nt * 2], bh[nt * 2 + 1]);
        #pragma unroll
        for (int nt = 0; nt < 8; nt++)
            mma16816(c2[nt], ah, bl[nt * 2], bl[nt * 2 + 1]);
        #pragma unroll
        for (int nt = 0; nt < 8; nt++)
            mma16816(c2[nt], al, bh[nt * 2], bh[nt * 2 + 1]);
    }

    // ---- epilogue: +b2, direct H store (32B sectors) ----
    #pragma unroll
    for (int nt = 0; nt < 8; nt++) {
        int c0 = nt * 8 + qd * 2;
        float hA0 = c2[nt][0] + b2s[c0], hA1 = c2[nt][1] + b2s[c0 + 1];
        float hB0 = c2[nt][2] + b2s[c0], hB1 = c2[nt][3] + b2s[c0 + 1];
        *(float2*)&g_H[(row0 + rA) * DS + c0] = make_float2(hA0, hA1);
        *(float2*)&g_H[(row0 + rB) * DS + c0] = make_float2(hB0, hB1);
    }
}

// ======================= K2 (unchanged, passing) =======================
__global__ __launch_bounds__(256) void k2_attn(
    const float* __restrict__ mask,
    float* __restrict__ out_sel, float* __restrict__ out_ctx,
    float* __restrict__ out_attn)
{
    __shared__ float sms[NS];
    __shared__ float ss[NS];
    __shared__ float aw[NS];
    __shared__ float red[256];
    __shared__ int   redi[256];
    __shared__ float cpart[4][DS];
    __shared__ int   idxs[KSEL];

    const int t = threadIdx.x;
    const int b = blockIdx.x;
    const float* sc = g_scores + (size_t)b * NS;
    const float* mk = mask + (size_t)b * NS;

    float lmax = -INFINITY;
    #pragma unroll
    for (int u = 0; u < 4; u++) {
        int s = t + 256 * u;
        float v = sc[s];
        float m = (mk[s] > 0.5f) ? v : -INFINITY;
        sms[s] = m;
        lmax = fmaxf(lmax, m);
    }
    red[t] = lmax;
    __syncthreads();
    for (int off = 128; off > 0; off >>= 1) {
        if (t < off) red[t] = fmaxf(red[t], red[t + off]);
        __syncthreads();
    }
    const float mx = red[0];
    const bool allm = !(mx > -INFINITY);
    __syncthreads();

    float lsum = 0.0f;
    #pragma unroll
    for (int u = 0; u < 4; u++) {
        int s = t + 256 * u;
        float m = sms[s];
        float e;
        if (allm)                e = 1.0f;
        else if (m == -INFINITY) e = 0.0f;
        else                     e = expf(m - mx);
        aw[s] = e;
        lsum += e;
    }
    red[t] = lsum;
    __syncthreads();
    for (int off = 128; off > 0; off >>= 1) {
        if (t < off) red[t] += red[t + off];
        __syncthreads();
    }
    const float inv = 1.0f / red[0];
    __syncthreads();
    #pragma unroll
    for (int u = 0; u < 4; u++) {
        int s = t + 256 * u;
        float w = aw[s] * inv;
        aw[s] = w;
        out_attn[(size_t)b * NS + s] = w;
        ss[s] = allm ? 0.0f : sms[s];
    }
    __syncthreads();

    const float* Hb = g_H + (size_t)b * NS * DS;
    {
        const int d = t & 63, part = t >> 6;
        float acc = 0.0f;
        const int s0 = part * 256;
        #pragma unroll 8
        for (int s = s0; s < s0 + 256; s++)
            acc += aw[s] * Hb[(size_t)s * DS + d];
        cpart[part][d] = acc;
    }
    __syncthreads();
    if (t < DS)
        out_ctx[(size_t)b * DS + t] =
            (cpart[0][t] + cpart[1][t]) + (cpart[2][t] + cpart[3][t]);

    for (int it = 0; it < KSEL; it++) {
        float bv = -INFINITY; int bi = 0x7fffffff;
        #pragma unroll
        for (int u = 0; u < 4; u++) {
            int s = t + 256 * u;
            float v = ss[s];
            if (v > bv || (v == bv && s < bi)) { bv = v; bi = s; }
        }
        red[t] = bv; redi[t] = bi;
        __syncthreads();
        for (int off = 128; off > 0; off >>= 1) {
            if (t < off) {
                float v2 = red[t + off]; int i2 = redi[t + off];
                if (v2 > red[t] || (v2 == red[t] && i2 < redi[t])) { red[t] = v2; redi[t] = i2; }
            }
            __syncthreads();
        }
        if (t == 0) { idxs[it] = redi[0]; ss[redi[0]] = -INFINITY; }
        __syncthreads();
    }

    for (int e = t; e < KSEL * DS; e += 256) {
        int j = e >> 6, d = e & 63;
        out_sel[((size_t)b * KSEL + j) * DS + d] = Hb[(size_t)idxs[j] * DS + d];
    }
}

// ============================================================================
extern "C" void kernel_launch(void* const* d_in, const int* in_sizes, int n_in,
                              void* d_out, int out_size) {
    const float* X    = (const float*)d_in[0];
    const float* mask = (const float*)d_in[1];
    const float* W1   = (const float*)d_in[2];
    const float* b1   = (const float*)d_in[3];
    const float* W2   = (const float*)d_in[4];
    const float* b2   = (const float*)d_in[5];
    const float* q    = (const float*)d_in[6];

    float* out      = (float*)d_out;
    float* out_sel  = out;
    float* out_ctx  = out + (size_t)NB * KSEL * DS;
    float* out_attn = out_ctx + (size_t)NB * DS;

    cudaFuncSetAttribute(k1_mlp, cudaFuncAttributeMaxDynamicSharedMemorySize, SM_TOTAL);

    k1_mlp<<<(NB * NS) / 128, 256, SM_TOTAL>>>(X, W1, b1, W2, b2, q);
    k2_attn<<<NB, 256>>>(mask, out_sel, out_ctx, out_attn);
}

// round 11
// speedup vs baseline: 2.1987x; 1.1327x over previous
#include <cuda_runtime.h>
#include <cuda_fp16.h>
#include <stdint.h>
#include <math.h>

#define NB 1024
#define NS 1024
#define DI 128
#define DS 64
#define KSEL 8

typedef unsigned long long ull;

__device__ float g_H[(size_t)NB * NS * DS];       // 256 MB
__device__ float g_scores[(size_t)NB * NS];       // 4 MB

// ======================= helpers =======================
__device__ __forceinline__ uint32_t smem_u32(const void* p) {
    uint32_t a;
    asm("{ .reg .u64 t; cvta.to.shared.u64 t, %1; cvt.u32.u64 %0, t; }" : "=r"(a) : "l"(p));
    return a;
}
// 2-way fp16 split: fp32 pair -> packed half2 (hi, lo residual). 22 mantissa
// bits total; 3-term product error ~2^-22 (fp32-class for this problem).
__device__ __forceinline__ void split2h(float a, float b, uint32_t& hi, uint32_t& lo) {
    __half2 h = __float22half2_rn(make_float2(a, b));
    float2 hf = __half22float2(h);
    __half2 l = __float22half2_rn(make_float2(a - hf.x, b - hf.y));
    hi = *reinterpret_cast<uint32_t*>(&h);
    lo = *reinterpret_cast<uint32_t*>(&l);
}
__device__ __forceinline__ void ldm4(uint32_t r[4], uint32_t addr) {
    asm volatile("ldmatrix.sync.aligned.m8n8.x4.shared.b16 {%0,%1,%2,%3}, [%4];"
        : "=r"(r[0]), "=r"(r[1]), "=r"(r[2]), "=r"(r[3]) : "r"(addr));
}
__device__ __forceinline__ void mma16816(float c[4], const uint32_t a[4],
                                         uint32_t b0, uint32_t b1) {
    asm volatile(
        "mma.sync.aligned.m16n8k16.row.col.f32.f16.f16.f32 "
        "{%0,%1,%2,%3}, {%4,%5,%6,%7}, {%8,%9}, {%0,%1,%2,%3};"
        : "+f"(c[0]), "+f"(c[1]), "+f"(c[2]), "+f"(c[3])
        : "r"(a[0]), "r"(a[1]), "r"(a[2]), "r"(a[3]), "r"(b0), "r"(b1));
}

// ======================= K1: split-fp16 HMMA MLP =======================
// smem (bytes):
//  XH @0     (16K) [128 r][64 k] fp16, 128B rows, chunk swizzle c^(r&7)
//  XL @16384 (16K)   (phase2: TH/TL overlay XH/XL)
//  W1H @32768 (8K) [64 n][64 k] per K-pass, 128B rows, swizzle kc^(n&7)
//  W1L @40960 (8K)
//  W2H @49152 (8K) [64 n][64 k]
//  W2L @57344 (8K)
//  WT @65536 (w~ = W2*qm + b2.qm slot; 272B), B1S @65808, B2S @66064 -> 66320
static constexpr int SM_XH = 0,      SM_XL = 16384;
static constexpr int SM_W1H = 32768, SM_W1L = 40960;
static constexpr int SM_W2H = 49152, SM_W2L = 57344;
static constexpr int SM_WT = 65536,  SM_B1S = 65808, SM_B2S = 66064;
static constexpr int SM_TOTAL = 66320;

__global__ __launch_bounds__(256, 2) void k1_mlp(
    const float* __restrict__ X,  const float* __restrict__ W1,
    const float* __restrict__ b1, const float* __restrict__ W2,
    const float* __restrict__ b2, const float* __restrict__ q)
{
    extern __shared__ __align__(16) char sm[];
    const uint32_t sb = smem_u32(sm);
    float* wt  = (float*)(sm + SM_WT);
    float* b1s = (float*)(sm + SM_B1S);
    float* b2s = (float*)(sm + SM_B2S);

    const int tid  = threadIdx.x;
    const int warp = tid >> 5, lane = tid & 31;
    const int grp  = lane >> 2, qd = lane & 3;
    const int warpR = warp * 16;
    const size_t row0 = (size_t)blockIdx.x * 128;

    // ---- preamble: biases, w~ = W2*qm (fp32), b2.qm ----
    if (tid < DS) {
        b1s[tid] = b1[tid];
        b2s[tid] = b2[tid];
        float acc = 0.0f;
        #pragma unroll 8
        for (int d = 0; d < DS; d++)
            acc += W2[(size_t)tid * DS + d] * (0.5f * (q[d] + q[DS + d]));
        wt[tid] = acc;
    } else if (tid == 64) {
        float acc = 0.0f;
        #pragma unroll 8
        for (int d = 0; d < DS; d++)
            acc += b2[d] * (0.5f * (q[d] + q[DS + d]));
        wt[64] = acc;
    }
    // ---- W2 -> [n][k] fp16 2-way split tiles ----
    #pragma unroll
    for (int i = 0; i < 2; i++) {
        int task = tid + 256 * i;           // 512 tasks: (n, kc) kc 0..7
        int n = task & 63, kc = task >> 6;
        uint32_t h[4], l[4];
        #pragma unroll
        for (int j = 0; j < 4; j++) {
            float v0 = W2[(size_t)(kc * 8 + j * 2 + 0) * DS + n];
            float v1 = W2[(size_t)(kc * 8 + j * 2 + 1) * DS + n];
            split2h(v0, v1, h[j], l[j]);
        }
        uint32_t off = (uint32_t)n * 128 + (uint32_t)((kc ^ (n & 7)) << 4);
        *(uint4*)(sm + SM_W2H + off) = make_uint4(h[0], h[1], h[2], h[3]);
        *(uint4*)(sm + SM_W2L + off) = make_uint4(l[0], l[1], l[2], l[3]);
    }

    float c1[8][4];
    #pragma unroll
    for (int nt = 0; nt < 8; nt++)
        #pragma unroll
        for (int j = 0; j < 4; j++) c1[nt][j] = 0.0f;

    // ================= GEMM1: two K=64 passes, fp16 2-way (3 terms) =================
    for (int p = 0; p < 2; p++) {
        float4 xa[4], xb[4];
        #pragma unroll
        for (int i = 0; i < 4; i++) {
            int task = tid + 256 * i;       // (r, c): 128 rows x 8 chunks
            int r = task >> 3, c = task & 7;
            const float* src = X + (row0 + r) * DI + p * 64 + c * 8;
            xa[i] = *(const float4*)src;
            xb[i] = *(const float4*)(src + 4);
        }
        float w1v[2][8];
        #pragma unroll
        for (int i = 0; i < 2; i++) {
            int task = tid + 256 * i;       // (n, kc): 64 x 8
            int n = task & 63, kc = task >> 6;
            #pragma unroll
            for (int j = 0; j < 8; j++)
                w1v[i][j] = W1[(size_t)(p * 64 + kc * 8 + j) * DS + n];
        }
        __syncthreads();    // prior smem reads complete
        #pragma unroll
        for (int i = 0; i < 4; i++) {
            int task = tid + 256 * i;
            int r = task >> 3, c = task & 7;
            uint32_t h[4], l[4];
            split2h(xa[i].x, xa[i].y, h[0], l[0]);
            split2h(xa[i].z, xa[i].w, h[1], l[1]);
            split2h(xb[i].x, xb[i].y, h[2], l[2]);
            split2h(xb[i].z, xb[i].w, h[3], l[3]);
            uint32_t off = (uint32_t)r * 128 + (uint32_t)((c ^ (r & 7)) << 4);
            *(uint4*)(sm + SM_XH + off) = make_uint4(h[0], h[1], h[2], h[3]);
            *(uint4*)(sm + SM_XL + off) = make_uint4(l[0], l[1], l[2], l[3]);
        }
        #pragma unroll
        for (int i = 0; i < 2; i++) {
            int task = tid + 256 * i;
            int n = task & 63, kc = task >> 6;
            uint32_t h[4], l[4];
            #pragma unroll
            for (int j = 0; j < 4; j++)
                split2h(w1v[i][j * 2], w1v[i][j * 2 + 1], h[j], l[j]);
            uint32_t off = (uint32_t)n * 128 + (uint32_t)((kc ^ (n & 7)) << 4);
            *(uint4*)(sm + SM_W1H + off) = make_uint4(h[0], h[1], h[2], h[3]);
            *(uint4*)(sm + SM_W1L + off) = make_uint4(l[0], l[1], l[2], l[3]);
        }
        __syncthreads();

        #pragma unroll
        for (int ks = 0; ks < 4; ks++) {
            uint32_t ah[4], al[4];
            {
                int seg = lane >> 3, ri = lane & 7;
                int r = warpR + (seg & 1) * 8 + ri;
                int c = 2 * ks + (seg >> 1);
                uint32_t off = (uint32_t)r * 128 + (uint32_t)((c ^ (r & 7)) << 4);
                ldm4(ah, sb + SM_XH + off);
                ldm4(al, sb + SM_XL + off);
            }
            uint32_t bh[16], bl[16];
            #pragma unroll
            for (int g = 0; g < 4; g++) {
                int seg = lane >> 3, ri = lane & 7;
                int n = (g * 2 + (seg >> 1)) * 8 + ri;
                int c = 2 * ks + (seg & 1);
                uint32_t off = (uint32_t)n * 128 + (uint32_t)((c ^ (n & 7)) << 4);
                ldm4(&bh[g * 4], sb + SM_W1H + off);
                ldm4(&bl[g * 4], sb + SM_W1L + off);
            }
            // term-major, nt-inner (independent accumulators back-to-back)
            #pragma unroll
            for (int nt = 0; nt < 8; nt++)   // hh
                mma16816(c1[nt], ah, bh[nt * 2], bh[nt * 2 + 1]);
            #pragma unroll
            for (int nt = 0; nt < 8; nt++)   // hl
                mma16816(c1[nt], ah, bl[nt * 2], bl[nt * 2 + 1]);
            #pragma unroll
            for (int nt = 0; nt < 8; nt++)   // lh
                mma16816(c1[nt], al, bh[nt * 2], bh[nt * 2 + 1]);
        }
    }
    __syncthreads();    // GEMM1 smem reads done; XH/XL become TH/TL

    // ---- relu + b1 -> fp32 score (w~) + fp16 2-way split -> T ----
    const int rA = warpR + grp, rB = rA + 8;
    {
        float pA = 0.0f, pB = 0.0f;
        #pragma unroll
        for (int nt = 0; nt < 8; nt++) {
            int c0 = nt * 8 + qd * 2;
            float t0 = fmaxf(c1[nt][0] + b1s[c0],     0.0f);
            float t1 = fmaxf(c1[nt][1] + b1s[c0 + 1], 0.0f);
            float t2 = fmaxf(c1[nt][2] + b1s[c0],     0.0f);
            float t3 = fmaxf(c1[nt][3] + b1s[c0 + 1], 0.0f);
            pA += t0 * wt[c0] + t1 * wt[c0 + 1];
            pB += t2 * wt[c0] + t3 * wt[c0 + 1];
            uint32_t h01, l01, h23, l23;
            split2h(t0, t1, h01, l01);
            split2h(t2, t3, h23, l23);
            uint32_t offA = (uint32_t)rA * 128 + (uint32_t)((nt ^ (rA & 7)) << 4) + qd * 4;
            uint32_t offB = (uint32_t)rB * 128 + (uint32_t)((nt ^ (rB & 7)) << 4) + qd * 4;
            *(uint32_t*)(sm + SM_XH + offA) = h01;
            *(uint32_t*)(sm + SM_XL + offA) = l01;
            *(uint32_t*)(sm + SM_XH + offB) = h23;
            *(uint32_t*)(sm + SM_XL + offB) = l23;
        }
        pA += __shfl_xor_sync(0xffffffffu, pA, 1);
        pA += __shfl_xor_sync(0xffffffffu, pA, 2);
        pB += __shfl_xor_sync(0xffffffffu, pB, 1);
        pB += __shfl_xor_sync(0xffffffffu, pB, 2);
        if (qd == 0) {
            float b2qm = wt[64];
            g_scores[row0 + rA] = (pA + b2qm) * 0.125f;
            g_scores[row0 + rB] = (pB + b2qm) * 0.125f;
        }
    }
    __syncthreads();

    // ================= GEMM2: H = T @ W2 + b2 (K=64, 3 terms) =================
    float c2[8][4];
    #pragma unroll
    for (int nt = 0; nt < 8; nt++)
        #pragma unroll
        for (int j = 0; j < 4; j++) c2[nt][j] = 0.0f;

    #pragma unroll
    for (int ks = 0; ks < 4; ks++) {
        uint32_t ah[4], al[4];
        {
            int seg = lane >> 3, ri = lane & 7;
            int r = warpR + (seg & 1) * 8 + ri;
            int c = 2 * ks + (seg >> 1);
            uint32_t off = (uint32_t)r * 128 + (uint32_t)((c ^ (r & 7)) << 4);
            ldm4(ah, sb + SM_XH + off);   // TH
            ldm4(al, sb + SM_XL + off);   // TL
        }
        uint32_t bh[16], bl[16];
        #pragma unroll
        for (int g = 0; g < 4; g++) {
            int seg = lane >> 3, ri = lane & 7;
            int n = (g * 2 + (seg >> 1)) * 8 + ri;
            int c = 2 * ks + (seg & 1);
            uint32_t off = (uint32_t)n * 128 + (uint32_t)((c ^ (n & 7)) << 4);
            ldm4(&bh[g * 4], sb + SM_W2H + off);
            ldm4(&bl[g * 4], sb + SM_W2L + off);
        }
        #pragma unroll
        for (int nt = 0; nt < 8; nt++)
            mma16816(c2[nt], ah, bh[nt * 2], bh[nt * 2 + 1]);
        #pragma unroll
        for (int nt = 0; nt < 8; nt++)
            mma16816(c2[nt], ah, bl[nt * 2], bl[nt * 2 + 1]);
        #pragma unroll
        for (int nt = 0; nt < 8; nt++)
            mma16816(c2[nt], al, bh[nt * 2], bh[nt * 2 + 1]);
    }

    // ---- epilogue: +b2, direct H store (32B sectors) ----
    #pragma unroll
    for (int nt = 0; nt < 8; nt++) {
        int c0 = nt * 8 + qd * 2;
        float hA0 = c2[nt][0] + b2s[c0], hA1 = c2[nt][1] + b2s[c0 + 1];
        float hB0 = c2[nt][2] + b2s[c0], hB1 = c2[nt][3] + b2s[c0 + 1];
        *(float2*)&g_H[(row0 + rA) * DS + c0] = make_float2(hA0, hA1);
        *(float2*)&g_H[(row0 + rB) * DS + c0] = make_float2(hB0, hB1);
    }
}

// ======================= K2 (unchanged, passing) =======================
__global__ __launch_bounds__(256) void k2_attn(
    const float* __restrict__ mask,
    float* __restrict__ out_sel, float* __restrict__ out_ctx,
    float* __restrict__ out_attn)
{
    __shared__ float sms[NS];
    __shared__ float ss[NS];
    __shared__ float aw[NS];
    __shared__ float red[256];
    __shared__ int   redi[256];
    __shared__ float cpart[4][DS];
    __shared__ int   idxs[KSEL];

    const int t = threadIdx.x;
    const int b = blockIdx.x;
    const float* sc = g_scores + (size_t)b * NS;
    const float* mk = mask + (size_t)b * NS;

    float lmax = -INFINITY;
    #pragma unroll
    for (int u = 0; u < 4; u++) {
        int s = t + 256 * u;
        float v = sc[s];
        float m = (mk[s] > 0.5f) ? v : -INFINITY;
        sms[s] = m;
        lmax = fmaxf(lmax, m);
    }
    red[t] = lmax;
    __syncthreads();
    for (int off = 128; off > 0; off >>= 1) {
        if (t < off) red[t] = fmaxf(red[t], red[t + off]);
        __syncthreads();
    }
    const float mx = red[0];
    const bool allm = !(mx > -INFINITY);
    __syncthreads();

    float lsum = 0.0f;
    #pragma unroll
    for (int u = 0; u < 4; u++) {
        int s = t + 256 * u;
        float m = sms[s];
        float e;
        if (allm)                e = 1.0f;
        else if (m == -INFINITY) e = 0.0f;
        else                     e = expf(m - mx);
        aw[s] = e;
        lsum += e;
    }
    red[t] = lsum;
    __syncthreads();
    for (int off = 128; off > 0; off >>= 1) {
        if (t < off) red[t] += red[t + off];
        __syncthreads();
    }
    const float inv = 1.0f / red[0];
    __syncthreads();
    #pragma unroll
    for (int u = 0; u < 4; u++) {
        int s = t + 256 * u;
        float w = aw[s] * inv;
        aw[s] = w;
        out_attn[(size_t)b * NS + s] = w;
        ss[s] = allm ? 0.0f : sms[s];
    }
    __syncthreads();

    const float* Hb = g_H + (size_t)b * NS * DS;
    {
        const int d = t & 63, part = t >> 6;
        float acc = 0.0f;
        const int s0 = part * 256;
        #pragma unroll 8
        for (int s = s0; s < s0 + 256; s++)
            acc += aw[s] * Hb[(size_t)s * DS + d];
        cpart[part][d] = acc;
    }
    __syncthreads();
    if (t < DS)
        out_ctx[(size_t)b * DS + t] =
            (cpart[0][t] + cpart[1][t]) + (cpart[2][t] + cpart[3][t]);

    for (int it = 0; it < KSEL; it++) {
        float bv = -INFINITY; int bi = 0x7fffffff;
        #pragma unroll
        for (int u = 0; u < 4; u++) {
            int s = t + 256 * u;
            float v = ss[s];
            if (v > bv || (v == bv && s < bi)) { bv = v; bi = s; }
        }
        red[t] = bv; redi[t] = bi;
        __syncthreads();
        for (int off = 128; off > 0; off >>= 1) {
            if (t < off) {
                float v2 = red[t + off]; int i2 = redi[t + off];
                if (v2 > red[t] || (v2 == red[t] && i2 < redi[t])) { red[t] = v2; redi[t] = i2; }
            }
            __syncthreads();
        }
        if (t == 0) { idxs[it] = redi[0]; ss[redi[0]] = -INFINITY; }
        __syncthreads();
    }

    for (int e = t; e < KSEL * DS; e += 256) {
        int j = e >> 6, d = e & 63;
        out_sel[((size_t)b * KSEL + j) * DS + d] = Hb[(size_t)idxs[j] * DS + d];
    }
}

// ============================================================================
extern "C" void kernel_launch(void* const* d_in, const int* in_sizes, int n_in,
                              void* d_out, int out_size) {
    const float* X    = (const float*)d_in[0];
    const float* mask = (const float*)d_in[1];
    const float* W1   = (const float*)d_in[2];
    const float* b1   = (const float*)d_in[3];
    const float* W2   = (const float*)d_in[4];
    const float* b2   = (const float*)d_in[5];
    const float* q    = (const float*)d_in[6];

    float* out      = (float*)d_out;
    float* out_sel  = out;
    float* out_ctx  = out + (size_t)NB * KSEL * DS;
    float* out_attn = out_ctx + (size_t)NB * DS;

    cudaFuncSetAttribute(k1_mlp, cudaFuncAttributeMaxDynamicSharedMemorySize, SM_TOTAL);

    k1_mlp<<<(NB * NS) / 128, 256, SM_TOTAL>>>(X, W1, b1, W2, b2, q);
    k2_attn<<<NB, 256>>>(mask, out_sel, out_ctx, out_attn);
}

// round 13
// speedup vs baseline: 2.3946x; 1.0891x over previous
#include <cuda_runtime.h>
#include <cuda_fp16.h>
#include <stdint.h>
#include <math.h>

#define NB 1024
#define NS 1024
#define DI 128
#define DS 64
#define KSEL 8

typedef unsigned long long ull;

__device__ float g_H[(size_t)NB * NS * DS];       // 256 MB
__device__ float g_scores[(size_t)NB * NS];       // 4 MB

// ======================= helpers =======================
__device__ __forceinline__ uint32_t smem_u32(const void* p) {
    uint32_t a;
    asm("{ .reg .u64 t; cvta.to.shared.u64 t, %1; cvt.u32.u64 %0, t; }" : "=r"(a) : "l"(p));
    return a;
}
// 2-way fp16 split: fp32 pair -> packed half2 (hi, lo residual). 22 mantissa
// bits; 3-term product error ~2^-22 (fp32-class for this problem).
__device__ __forceinline__ void split2h(float a, float b, uint32_t& hi, uint32_t& lo) {
    __half2 h = __float22half2_rn(make_float2(a, b));
    float2 hf = __half22float2(h);
    __half2 l = __float22half2_rn(make_float2(a - hf.x, b - hf.y));
    hi = *reinterpret_cast<uint32_t*>(&h);
    lo = *reinterpret_cast<uint32_t*>(&l);
}
__device__ __forceinline__ void ldm4(uint32_t r[4], uint32_t addr) {
    asm volatile("ldmatrix.sync.aligned.m8n8.x4.shared.b16 {%0,%1,%2,%3}, [%4];"
        : "=r"(r[0]), "=r"(r[1]), "=r"(r[2]), "=r"(r[3]) : "r"(addr));
}
__device__ __forceinline__ void mma16816(float c[4], const uint32_t a[4],
                                         uint32_t b0, uint32_t b1) {
    asm volatile(
        "mma.sync.aligned.m16n8k16.row.col.f32.f16.f16.f32 "
        "{%0,%1,%2,%3}, {%4,%5,%6,%7}, {%8,%9}, {%0,%1,%2,%3};"
        : "+f"(c[0]), "+f"(c[1]), "+f"(c[2]), "+f"(c[3])
        : "r"(a[0]), "r"(a[1]), "r"(a[2]), "r"(a[3]), "r"(b0), "r"(b1));
}

// ======================= K1: register-resident split-fp16 HMMA MLP ==========
// A-side (X rows, T) is warp-exclusive -> lives in registers only.
// B-side (weights) split once into smem, ONE __syncthreads total.
// smem (bytes):
//  W1H @0     (16K) [64 n][128 k] fp16, 256B rows, chunk swizzle kc^(n&7)
//  W1L @16384 (16K)
//  W2H @32768 (8K)  [64 n][64 k] fp16, 128B rows
//  W2L @40960 (8K)
//  WT  @49152 (272: w~ = W2*qm, + b2.qm at [64])
//  B1S @49424 (256), B2S @49680 (256) -> total 49936
static constexpr int SM_W1H = 0,     SM_W1L = 16384;
static constexpr int SM_W2H = 32768, SM_W2L = 40960;
static constexpr int SM_WT = 49152,  SM_B1S = 49424, SM_B2S = 49680;
static constexpr int SM_TOTAL = 49936;

__global__ __launch_bounds__(256, 2) void k1_mlp(
    const float* __restrict__ X,  const float* __restrict__ W1,
    const float* __restrict__ b1, const float* __restrict__ W2,
    const float* __restrict__ b2, const float* __restrict__ q)
{
    extern __shared__ __align__(16) char sm[];
    const uint32_t sb = smem_u32(sm);
    float* wt  = (float*)(sm + SM_WT);
    float* b1s = (float*)(sm + SM_B1S);
    float* b2s = (float*)(sm + SM_B2S);

    const int tid  = threadIdx.x;
    const int warp = tid >> 5, lane = tid & 31;
    const int grp  = lane >> 2, qd = lane & 3;
    const int seg  = lane >> 3, ri = lane & 7;
    const int rA = warp * 16 + grp, rB = rA + 8;
    const size_t row0 = (size_t)blockIdx.x * 128;

    // ---- cooperative preamble: biases, w~ = W2*qm (fp32), b2.qm ----
    if (tid < DS) {
        b1s[tid] = b1[tid];
        b2s[tid] = b2[tid];
        float acc = 0.0f;
        #pragma unroll 8
        for (int d = 0; d < DS; d++)
            acc += W2[(size_t)tid * DS + d] * (0.5f * (q[d] + q[DS + d]));
        wt[tid] = acc;
    } else if (tid == 64) {
        float acc = 0.0f;
        #pragma unroll 8
        for (int d = 0; d < DS; d++)
            acc += b2[d] * (0.5f * (q[d] + q[DS + d]));
        wt[64] = acc;
    }
    // ---- W1 -> [n][128k] fp16 split tiles (full K; transpose during load) ----
    #pragma unroll
    for (int i = 0; i < 4; i++) {
        int task = tid + 256 * i;           // 1024 tasks: (n, kc) kc 0..15
        int n = task & 63, kc = task >> 6;
        uint32_t h[4], l[4];
        #pragma unroll
        for (int j = 0; j < 4; j++) {
            float v0 = W1[(size_t)(kc * 8 + j * 2 + 0) * DS + n];
            float v1 = W1[(size_t)(kc * 8 + j * 2 + 1) * DS + n];
            split2h(v0, v1, h[j], l[j]);
        }
        uint32_t off = (uint32_t)n * 256 + (uint32_t)((kc ^ (n & 7)) << 4);
        *(uint4*)(sm + SM_W1H + off) = make_uint4(h[0], h[1], h[2], h[3]);
        *(uint4*)(sm + SM_W1L + off) = make_uint4(l[0], l[1], l[2], l[3]);
    }
    // ---- W2 -> [n][64k] fp16 split tiles ----
    #pragma unroll
    for (int i = 0; i < 2; i++) {
        int task = tid + 256 * i;           // 512 tasks: (n, kc) kc 0..7
        int n = task & 63, kc = task >> 6;
        uint32_t h[4], l[4];
        #pragma unroll
        for (int j = 0; j < 4; j++) {
            float v0 = W2[(size_t)(kc * 8 + j * 2 + 0) * DS + n];
            float v1 = W2[(size_t)(kc * 8 + j * 2 + 1) * DS + n];
            split2h(v0, v1, h[j], l[j]);
        }
        uint32_t off = (uint32_t)n * 128 + (uint32_t)((kc ^ (n & 7)) << 4);
        *(uint4*)(sm + SM_W2H + off) = make_uint4(h[0], h[1], h[2], h[3]);
        *(uint4*)(sm + SM_W2L + off) = make_uint4(l[0], l[1], l[2], l[3]);
    }

    // X fragment pointers (A-side is warp-exclusive: direct global -> regs)
    const float* XrA = X + (row0 + rA) * DI + 2 * qd;
    const float* XrB = X + (row0 + rB) * DI + 2 * qd;

    // prefetch k-chunk 0 (overlaps the weight-store phase of other threads)
    float2 pa0 = *(const float2*)(XrA);
    float2 pb0 = *(const float2*)(XrB);
    float2 pa8 = *(const float2*)(XrA + 8);
    float2 pb8 = *(const float2*)(XrB + 8);

    __syncthreads();   // the ONLY barrier: weights visible to all warps

    float c1[8][4];
    #pragma unroll
    for (int nt = 0; nt < 8; nt++)
        #pragma unroll
        for (int j = 0; j < 4; j++) c1[nt][j] = 0.0f;

    // ================= GEMM1: K=128, 8 chunks, 3 terms (hh, hl, lh) ==========
    #pragma unroll
    for (int ks = 0; ks < 8; ks++) {
        float2 ca0 = pa0, cb0 = pb0, ca8 = pa8, cb8 = pb8;
        if (ks < 7) {
            int o = 16 * (ks + 1);
            pa0 = *(const float2*)(XrA + o);
            pb0 = *(const float2*)(XrB + o);
            pa8 = *(const float2*)(XrA + o + 8);
            pb8 = *(const float2*)(XrB + o + 8);
        }
        uint32_t ah[4], al[4];
        split2h(ca0.x, ca0.y, ah[0], al[0]);
        split2h(cb0.x, cb0.y, ah[1], al[1]);
        split2h(ca8.x, ca8.y, ah[2], al[2]);
        split2h(cb8.x, cb8.y, ah[3], al[3]);

        uint32_t bh[16], bl[16];
        #pragma unroll
        for (int g = 0; g < 4; g++) {
            int n = (g * 2 + (seg >> 1)) * 8 + ri;
            int c = 2 * ks + (seg & 1);
            uint32_t off = (uint32_t)n * 256 + (uint32_t)((c ^ (n & 7)) << 4);
            ldm4(&bh[g * 4], sb + SM_W1H + off);
            ldm4(&bl[g * 4], sb + SM_W1L + off);
        }
        #pragma unroll
        for (int nt = 0; nt < 8; nt++)   // hh
            mma16816(c1[nt], ah, bh[nt * 2], bh[nt * 2 + 1]);
        #pragma unroll
        for (int nt = 0; nt < 8; nt++)   // hl
            mma16816(c1[nt], ah, bl[nt * 2], bl[nt * 2 + 1]);
        #pragma unroll
        for (int nt = 0; nt < 8; nt++)   // lh
            mma16816(c1[nt], al, bh[nt * 2], bh[nt * 2 + 1]);
    }

    // ---- relu + b1 -> fp32 scores (w~) + in-register fp16 T fragments ----
    uint32_t th01[8], th23[8], tl01[8], tl23[8];
    {
        float pA = 0.0f, pB = 0.0f;
        #pragma unroll
        for (int nt = 0; nt < 8; nt++) {
            int c0 = nt * 8 + qd * 2;
            float t0 = fmaxf(c1[nt][0] + b1s[c0],     0.0f);
            float t1 = fmaxf(c1[nt][1] + b1s[c0 + 1], 0.0f);
            float t2 = fmaxf(c1[nt][2] + b1s[c0],     0.0f);
            float t3 = fmaxf(c1[nt][3] + b1s[c0 + 1], 0.0f);
            pA += t0 * wt[c0] + t1 * wt[c0 + 1];
            pB += t2 * wt[c0] + t3 * wt[c0 + 1];
            split2h(t0, t1, th01[nt], tl01[nt]);
            split2h(t2, t3, th23[nt], tl23[nt]);
        }
        pA += __shfl_xor_sync(0xffffffffu, pA, 1);
        pA += __shfl_xor_sync(0xffffffffu, pA, 2);
        pB += __shfl_xor_sync(0xffffffffu, pB, 1);
        pB += __shfl_xor_sync(0xffffffffu, pB, 2);
        if (qd == 0) {
            float b2qm = wt[64];
            g_scores[row0 + rA] = (pA + b2qm) * 0.125f;
            g_scores[row0 + rB] = (pB + b2qm) * 0.125f;
        }
    }

    // ================= GEMM2: H = T @ W2 + b2 (K=64, T in registers) =========
    float c2[8][4];
    #pragma unroll
    for (int nt = 0; nt < 8; nt++)
        #pragma unroll
        for (int j = 0; j < 4; j++) c2[nt][j] = 0.0f;

    #pragma unroll
    for (int ks = 0; ks < 4; ks++) {
        uint32_t ah[4] = {th01[2 * ks], th23[2 * ks], th01[2 * ks + 1], th23[2 * ks + 1]};
        uint32_t al[4] = {tl01[2 * ks], tl23[2 * ks], tl01[2 * ks + 1], tl23[2 * ks + 1]};
        uint32_t bh[16], bl[16];
        #pragma unroll
        for (int g = 0; g < 4; g++) {
            int n = (g * 2 + (seg >> 1)) * 8 + ri;
            int c = 2 * ks + (seg & 1);
            uint32_t off = (uint32_t)n * 128 + (uint32_t)((c ^ (n & 7)) << 4);
            ldm4(&bh[g * 4], sb + SM_W2H + off);
            ldm4(&bl[g * 4], sb + SM_W2L + off);
        }
        #pragma unroll
        for (int nt = 0; nt < 8; nt++)
            mma16816(c2[nt], ah, bh[nt * 2], bh[nt * 2 + 1]);
        #pragma unroll
        for (int nt = 0; nt < 8; nt++)
            mma16816(c2[nt], ah, bl[nt * 2], bl[nt * 2 + 1]);
        #pragma unroll
        for (int nt = 0; nt < 8; nt++)
            mma16816(c2[nt], al, bh[nt * 2], bh[nt * 2 + 1]);
    }

    // ---- epilogue: +b2, direct H store (32B sectors per 4-lane group) ----
    #pragma unroll
    for (int nt = 0; nt < 8; nt++) {
        int c0 = nt * 8 + qd * 2;
        float hA0 = c2[nt][0] + b2s[c0], hA1 = c2[nt][1] + b2s[c0 + 1];
        float hB0 = c2[nt][2] + b2s[c0], hB1 = c2[nt][3] + b2s[c0 + 1];
        *(float2*)&g_H[(row0 + rA) * DS + c0] = make_float2(hA0, hA1);
        *(float2*)&g_H[(row0 + rB) * DS + c0] = make_float2(hB0, hB1);
    }
}

// ======================= K2 (unchanged, passing) =======================
__global__ __launch_bounds__(256) void k2_attn(
    const float* __restrict__ mask,
    float* __restrict__ out_sel, float* __restrict__ out_ctx,
    float* __restrict__ out_attn)
{
    __shared__ float sms[NS];
    __shared__ float ss[NS];
    __shared__ float aw[NS];
    __shared__ float red[256];
    __shared__ int   redi[256];
    __shared__ float cpart[4][DS];
    __shared__ int   idxs[KSEL];

    const int t = threadIdx.x;
    const int b = blockIdx.x;
    const float* sc = g_scores + (size_t)b * NS;
    const float* mk = mask + (size_t)b * NS;

    float lmax = -INFINITY;
    #pragma unroll
    for (int u = 0; u < 4; u++) {
        int s = t + 256 * u;
        float v = sc[s];
        float m = (mk[s] > 0.5f) ? v : -INFINITY;
        sms[s] = m;
        lmax = fmaxf(lmax, m);
    }
    red[t] = lmax;
    __syncthreads();
    for (int off = 128; off > 0; off >>= 1) {
        if (t < off) red[t] = fmaxf(red[t], red[t + off]);
        __syncthreads();
    }
    const float mx = red[0];
    const bool allm = !(mx > -INFINITY);
    __syncthreads();

    float lsum = 0.0f;
    #pragma unroll
    for (int u = 0; u < 4; u++) {
        int s = t + 256 * u;
        float m = sms[s];
        float e;
        if (allm)                e = 1.0f;
        else if (m == -INFINITY) e = 0.0f;
        else                     e = expf(m - mx);
        aw[s] = e;
        lsum += e;
    }
    red[t] = lsum;
    __syncthreads();
    for (int off = 128; off > 0; off >>= 1) {
        if (t < off) red[t] += red[t + off];
        __syncthreads();
    }
    const float inv = 1.0f / red[0];
    __syncthreads();
    #pragma unroll
    for (int u = 0; u < 4; u++) {
        int s = t + 256 * u;
        float w = aw[s] * inv;
        aw[s] = w;
        out_attn[(size_t)b * NS + s] = w;
        ss[s] = allm ? 0.0f : sms[s];
    }
    __syncthreads();

    const float* Hb = g_H + (size_t)b * NS * DS;
    {
        const int d = t & 63, part = t >> 6;
        float acc = 0.0f;
        const int s0 = part * 256;
        #pragma unroll 8
        for (int s = s0; s < s0 + 256; s++)
            acc += aw[s] * Hb[(size_t)s * DS + d];
        cpart[part][d] = acc;
    }
    __syncthreads();
    if (t < DS)
        out_ctx[(size_t)b * DS + t] =
            (cpart[0][t] + cpart[1][t]) + (cpart[2][t] + cpart[3][t]);

    for (int it = 0; it < KSEL; it++) {
        float bv = -INFINITY; int bi = 0x7fffffff;
        #pragma unroll
        for (int u = 0; u < 4; u++) {
            int s = t + 256 * u;
            float v = ss[s];
            if (v > bv || (v == bv && s < bi)) { bv = v; bi = s; }
        }
        red[t] = bv; redi[t] = bi;
        __syncthreads();
        for (int off = 128; off > 0; off >>= 1) {
            if (t < off) {
                float v2 = red[t + off]; int i2 = redi[t + off];
                if (v2 > red[t] || (v2 == red[t] && i2 < redi[t])) { red[t] = v2; redi[t] = i2; }
            }
            __syncthreads();
        }
        if (t == 0) { idxs[it] = redi[0]; ss[redi[0]] = -INFINITY; }
        __syncthreads();
    }

    for (int e = t; e < KSEL * DS; e += 256) {
        int j = e >> 6, d = e & 63;
        out_sel[((size_t)b * KSEL + j) * DS + d] = Hb[(size_t)idxs[j] * DS + d];
    }
}

// ============================================================================
extern "C" void kernel_launch(void* const* d_in, const int* in_sizes, int n_in,
                              void* d_out, int out_size) {
    const float* X    = (const float*)d_in[0];
    const float* mask = (const float*)d_in[1];
    const float* W1   = (const float*)d_in[2];
    const float* b1   = (const float*)d_in[3];
    const float* W2   = (const float*)d_in[4];
    const float* b2   = (const float*)d_in[5];
    const float* q    = (const float*)d_in[6];

    float* out      = (float*)d_out;
    float* out_sel  = out;
    float* out_ctx  = out + (size_t)NB * KSEL * DS;
    float* out_attn = out_ctx + (size_t)NB * DS;

    cudaFuncSetAttribute(k1_mlp, cudaFuncAttributeMaxDynamicSharedMemorySize, SM_TOTAL);

    k1_mlp<<<(NB * NS) / 128, 256, SM_TOTAL>>>(X, W1, b1, W2, b2, q);
    k2_attn<<<NB, 256>>>(mask, out_sel, out_ctx, out_attn);
}

// round 14
// speedup vs baseline: 3.2748x; 1.3676x over previous
#include <cuda_runtime.h>
#include <cuda_fp16.h>
#include <stdint.h>
#include <math.h>

#define NB 1024
#define NS 1024
#define DI 128
#define DS 64
#define KSEL 8

typedef unsigned long long ull;

__device__ float g_H[(size_t)NB * NS * DS];       // 256 MB
__device__ float g_scores[(size_t)NB * NS];       // 4 MB

// pre-split, pre-swizzled weights (written once per call by k0_setup)
__device__ uint4 g_w1h[1024], g_w1l[1024];        // 16 KB each
__device__ uint4 g_w2h[512],  g_w2l[512];         // 8 KB each
__device__ float g_wt[65];                        // w~ = W2*qm, [64] = b2.qm
__device__ float g_b1s[64], g_b2s[64];

// ======================= helpers =======================
__device__ __forceinline__ uint32_t smem_u32(const void* p) {
    uint32_t a;
    asm("{ .reg .u64 t; cvta.to.shared.u64 t, %1; cvt.u32.u64 %0, t; }" : "=r"(a) : "l"(p));
    return a;
}
// 2-way fp16 split: fp32 pair -> packed half2 (hi, lo residual). 22 mantissa
// bits; 3-term product error ~2^-22 (fp32-class for this problem).
__device__ __forceinline__ void split2h(float a, float b, uint32_t& hi, uint32_t& lo) {
    __half2 h = __float22half2_rn(make_float2(a, b));
    float2 hf = __half22float2(h);
    __half2 l = __float22half2_rn(make_float2(a - hf.x, b - hf.y));
    hi = *reinterpret_cast<uint32_t*>(&h);
    lo = *reinterpret_cast<uint32_t*>(&l);
}
__device__ __forceinline__ void ldm4(uint32_t r[4], uint32_t addr) {
    asm volatile("ldmatrix.sync.aligned.m8n8.x4.shared.b16 {%0,%1,%2,%3}, [%4];"
        : "=r"(r[0]), "=r"(r[1]), "=r"(r[2]), "=r"(r[3]) : "r"(addr));
}
__device__ __forceinline__ void mma16816(float c[4], const uint32_t a[4],
                                         uint32_t b0, uint32_t b1) {
    asm volatile(
        "mma.sync.aligned.m16n8k16.row.col.f32.f16.f16.f32 "
        "{%0,%1,%2,%3}, {%4,%5,%6,%7}, {%8,%9}, {%0,%1,%2,%3};"
        : "+f"(c[0]), "+f"(c[1]), "+f"(c[2]), "+f"(c[3])
        : "r"(a[0]), "r"(a[1]), "r"(a[2]), "r"(a[3]), "r"(b0), "r"(b1));
}

// ======================= K0: one-time weight split =======================
// grid 4 x 256. Block b: W1 tasks [b*256, b*256+256), W2 tasks [b*128, +128).
// Block 0 additionally computes w~/b1/b2.
__global__ __launch_bounds__(256) void k0_setup(
    const float* __restrict__ W1, const float* __restrict__ b1,
    const float* __restrict__ W2, const float* __restrict__ b2,
    const float* __restrict__ q)
{
    const int tid = threadIdx.x, blk = blockIdx.x;
    {   // W1 -> [n][128k] split tiles, swizzled layout (idx = n*16 + (kc^(n&7)))
        int task = blk * 256 + tid;
        int n = task & 63, kc = task >> 6;
        uint32_t h[4], l[4];
        #pragma unroll
        for (int j = 0; j < 4; j++) {
            float v0 = W1[(size_t)(kc * 8 + j * 2 + 0) * DS + n];
            float v1 = W1[(size_t)(kc * 8 + j * 2 + 1) * DS + n];
            split2h(v0, v1, h[j], l[j]);
        }
        int idx = n * 16 + (kc ^ (n & 7));
        g_w1h[idx] = make_uint4(h[0], h[1], h[2], h[3]);
        g_w1l[idx] = make_uint4(l[0], l[1], l[2], l[3]);
    }
    if (tid < 128) {   // W2 -> [n][64k] split tiles (idx = n*8 + (kc^(n&7)))
        int task = blk * 128 + tid;
        int n = task & 63, kc = task >> 6;
        uint32_t h[4], l[4];
        #pragma unroll
        for (int j = 0; j < 4; j++) {
            float v0 = W2[(size_t)(kc * 8 + j * 2 + 0) * DS + n];
            float v1 = W2[(size_t)(kc * 8 + j * 2 + 1) * DS + n];
            split2h(v0, v1, h[j], l[j]);
        }
        int idx = n * 8 + (kc ^ (n & 7));
        g_w2h[idx] = make_uint4(h[0], h[1], h[2], h[3]);
        g_w2l[idx] = make_uint4(l[0], l[1], l[2], l[3]);
    }
    if (blk == 0) {
        if (tid < DS) {
            g_b1s[tid] = b1[tid];
            g_b2s[tid] = b2[tid];
            float acc = 0.0f;
            #pragma unroll 8
            for (int d = 0; d < DS; d++)
                acc += W2[(size_t)tid * DS + d] * (0.5f * (q[d] + q[DS + d]));
            g_wt[tid] = acc;
        } else if (tid == 64) {
            float acc = 0.0f;
            #pragma unroll 8
            for (int d = 0; d < DS; d++)
                acc += b2[d] * (0.5f * (q[d] + q[DS + d]));
            g_wt[64] = acc;
        }
    }
}

// ======================= K1: register-resident split-fp16 HMMA MLP ==========
// smem (bytes):
//  W1H @0     (16K) [64 n][128 k] fp16, 256B rows, chunk swizzle kc^(n&7)
//  W1L @16384 (16K)
//  W2H @32768 (8K)  [64 n][64 k] fp16, 128B rows
//  W2L @40960 (8K)
//  WT  @49152 (272), B1S @49424 (256), B2S @49680 (256) -> total 49936
static constexpr int SM_W1H = 0,     SM_W1L = 16384;
static constexpr int SM_W2H = 32768, SM_W2L = 40960;
static constexpr int SM_WT = 49152,  SM_B1S = 49424, SM_B2S = 49680;
static constexpr int SM_TOTAL = 49936;

__global__ __launch_bounds__(256, 2) void k1_mlp(
    const float* __restrict__ X, int blk0)
{
    extern __shared__ __align__(16) char sm[];
    const uint32_t sb = smem_u32(sm);
    float* wt  = (float*)(sm + SM_WT);
    float* b1s = (float*)(sm + SM_B1S);
    float* b2s = (float*)(sm + SM_B2S);

    const int tid  = threadIdx.x;
    const int warp = tid >> 5, lane = tid & 31;
    const int grp  = lane >> 2, qd = lane & 3;
    const int seg  = lane >> 3, ri = lane & 7;
    const int rA = warp * 16 + grp, rB = rA + 8;
    const size_t row0 = (size_t)(blockIdx.x + blk0) * 128;

    // ---- prologue: plain L2-hot copy of pre-split weights into smem ----
    #pragma unroll
    for (int i = 0; i < 4; i++) {
        int idx = tid + 256 * i;
        ((uint4*)(sm + SM_W1H))[idx] = g_w1h[idx];
        ((uint4*)(sm + SM_W1L))[idx] = g_w1l[idx];
    }
    #pragma unroll
    for (int i = 0; i < 2; i++) {
        int idx = tid + 256 * i;
        ((uint4*)(sm + SM_W2H))[idx] = g_w2h[idx];
        ((uint4*)(sm + SM_W2L))[idx] = g_w2l[idx];
    }
    if (tid < 65) wt[tid] = g_wt[tid];
    if (tid < 64) { b1s[tid] = g_b1s[tid]; b2s[tid] = g_b2s[tid]; }

    // X fragment pointers (A-side is warp-exclusive: direct global -> regs)
    const float* XrA = X + (row0 + rA) * DI + 2 * qd;
    const float* XrB = X + (row0 + rB) * DI + 2 * qd;

    // prefetch k-chunk 0 (overlaps weight-copy latency)
    float2 pa0 = *(const float2*)(XrA);
    float2 pb0 = *(const float2*)(XrB);
    float2 pa8 = *(const float2*)(XrA + 8);
    float2 pb8 = *(const float2*)(XrB + 8);

    __syncthreads();   // the ONLY barrier: weights visible to all warps

    float c1[8][4];
    #pragma unroll
    for (int nt = 0; nt < 8; nt++)
        #pragma unroll
        for (int j = 0; j < 4; j++) c1[nt][j] = 0.0f;

    // ================= GEMM1: K=128, 8 chunks, 3 terms (hh, hl, lh) ==========
    #pragma unroll
    for (int ks = 0; ks < 8; ks++) {
        float2 ca0 = pa0, cb0 = pb0, ca8 = pa8, cb8 = pb8;
        if (ks < 7) {
            int o = 16 * (ks + 1);
            pa0 = *(const float2*)(XrA + o);
            pb0 = *(const float2*)(XrB + o);
            pa8 = *(const float2*)(XrA + o + 8);
            pb8 = *(const float2*)(XrB + o + 8);
        }
        uint32_t ah[4], al[4];
        split2h(ca0.x, ca0.y, ah[0], al[0]);
        split2h(cb0.x, cb0.y, ah[1], al[1]);
        split2h(ca8.x, ca8.y, ah[2], al[2]);
        split2h(cb8.x, cb8.y, ah[3], al[3]);

        uint32_t bh[16], bl[16];
        #pragma unroll
        for (int g = 0; g < 4; g++) {
            int n = (g * 2 + (seg >> 1)) * 8 + ri;
            int c = 2 * ks + (seg & 1);
            uint32_t off = (uint32_t)n * 256 + (uint32_t)((c ^ (n & 7)) << 4);
            ldm4(&bh[g * 4], sb + SM_W1H + off);
            ldm4(&bl[g * 4], sb + SM_W1L + off);
        }
        #pragma unroll
        for (int nt = 0; nt < 8; nt++)   // hh
            mma16816(c1[nt], ah, bh[nt * 2], bh[nt * 2 + 1]);
        #pragma unroll
        for (int nt = 0; nt < 8; nt++)   // hl
            mma16816(c1[nt], ah, bl[nt * 2], bl[nt * 2 + 1]);
        #pragma unroll
        for (int nt = 0; nt < 8; nt++)   // lh
            mma16816(c1[nt], al, bh[nt * 2], bh[nt * 2 + 1]);
    }

    // ---- relu + b1 -> fp32 scores (w~) + in-register fp16 T fragments ----
    uint32_t th01[8], th23[8], tl01[8], tl23[8];
    {
        float pA = 0.0f, pB = 0.0f;
        #pragma unroll
        for (int nt = 0; nt < 8; nt++) {
            int c0 = nt * 8 + qd * 2;
            float t0 = fmaxf(c1[nt][0] + b1s[c0],     0.0f);
            float t1 = fmaxf(c1[nt][1] + b1s[c0 + 1], 0.0f);
            float t2 = fmaxf(c1[nt][2] + b1s[c0],     0.0f);
            float t3 = fmaxf(c1[nt][3] + b1s[c0 + 1], 0.0f);
            pA += t0 * wt[c0] + t1 * wt[c0 + 1];
            pB += t2 * wt[c0] + t3 * wt[c0 + 1];
            split2h(t0, t1, th01[nt], tl01[nt]);
            split2h(t2, t3, th23[nt], tl23[nt]);
        }
        pA += __shfl_xor_sync(0xffffffffu, pA, 1);
        pA += __shfl_xor_sync(0xffffffffu, pA, 2);
        pB += __shfl_xor_sync(0xffffffffu, pB, 1);
        pB += __shfl_xor_sync(0xffffffffu, pB, 2);
        if (qd == 0) {
            float b2qm = wt[64];
            g_scores[row0 + rA] = (pA + b2qm) * 0.125f;
            g_scores[row0 + rB] = (pB + b2qm) * 0.125f;
        }
    }

    // ================= GEMM2: H = T @ W2 + b2 (K=64, T in registers) =========
    float c2[8][4];
    #pragma unroll
    for (int nt = 0; nt < 8; nt++)
        #pragma unroll
        for (int j = 0; j < 4; j++) c2[nt][j] = 0.0f;

    #pragma unroll
    for (int ks = 0; ks < 4; ks++) {
        uint32_t ah[4] = {th01[2 * ks], th23[2 * ks], th01[2 * ks + 1], th23[2 * ks + 1]};
        uint32_t al[4] = {tl01[2 * ks], tl23[2 * ks], tl01[2 * ks + 1], tl23[2 * ks + 1]};
        uint32_t bh[16], bl[16];
        #pragma unroll
        for (int g = 0; g < 4; g++) {
            int n = (g * 2 + (seg >> 1)) * 8 + ri;
            int c = 2 * ks + (seg & 1);
            uint32_t off = (uint32_t)n * 128 + (uint32_t)((c ^ (n & 7)) << 4);
            ldm4(&bh[g * 4], sb + SM_W2H + off);
            ldm4(&bl[g * 4], sb + SM_W2L + off);
        }
        #pragma unroll
        for (int nt = 0; nt < 8; nt++)
            mma16816(c2[nt], ah, bh[nt * 2], bh[nt * 2 + 1]);
        #pragma unroll
        for (int nt = 0; nt < 8; nt++)
            mma16816(c2[nt], ah, bl[nt * 2], bl[nt * 2 + 1]);
        #pragma unroll
        for (int nt = 0; nt < 8; nt++)
            mma16816(c2[nt], al, bh[nt * 2], bh[nt * 2 + 1]);
    }

    // ---- epilogue: +b2, direct H store (32B sectors per 4-lane group) ----
    #pragma unroll
    for (int nt = 0; nt < 8; nt++) {
        int c0 = nt * 8 + qd * 2;
        float hA0 = c2[nt][0] + b2s[c0], hA1 = c2[nt][1] + b2s[c0 + 1];
        float hB0 = c2[nt][2] + b2s[c0], hB1 = c2[nt][3] + b2s[c0 + 1];
        *(float2*)&g_H[(row0 + rA) * DS + c0] = make_float2(hA0, hA1);
        *(float2*)&g_H[(row0 + rB) * DS + c0] = make_float2(hB0, hB1);
    }
}

// ======================= K2: softmax + ctx + top-8 + gather ==================
__global__ __launch_bounds__(256) void k2_attn(
    const float* __restrict__ mask,
    float* __restrict__ out_sel, float* __restrict__ out_ctx,
    float* __restrict__ out_attn)
{
    __shared__ float sms[NS];
    __shared__ float ss[NS];
    __shared__ float aw[NS];
    __shared__ float red[256];
    __shared__ int   redi[256];
    __shared__ float cpart[4][DS];
    __shared__ int   idxs[KSEL];

    const int t = threadIdx.x;
    const int b = blockIdx.x;
    const float* sc = g_scores + (size_t)b * NS;
    const float* mk = mask + (size_t)b * NS;

    float lmax = -INFINITY;
    #pragma unroll
    for (int u = 0; u < 4; u++) {
        int s = t + 256 * u;
        float v = sc[s];
        float m = (mk[s] > 0.5f) ? v : -INFINITY;
        sms[s] = m;
        lmax = fmaxf(lmax, m);
    }
    red[t] = lmax;
    __syncthreads();
    for (int off = 128; off > 0; off >>= 1) {
        if (t < off) red[t] = fmaxf(red[t], red[t + off]);
        __syncthreads();
    }
    const float mx = red[0];
    const bool allm = !(mx > -INFINITY);
    __syncthreads();

    float lsum = 0.0f;
    #pragma unroll
    for (int u = 0; u < 4; u++) {
        int s = t + 256 * u;
        float m = sms[s];
        float e;
        if (allm)                e = 1.0f;
        else if (m == -INFINITY) e = 0.0f;
        else                     e = expf(m - mx);
        aw[s] = e;
        lsum += e;
    }
    red[t] = lsum;
    __syncthreads();
    for (int off = 128; off > 0; off >>= 1) {
        if (t < off) red[t] += red[t + off];
        __syncthreads();
    }
    const float inv = 1.0f / red[0];
    __syncthreads();
    #pragma unroll
    for (int u = 0; u < 4; u++) {
        int s = t + 256 * u;
        float w = aw[s] * inv;
        aw[s] = w;
        out_attn[(size_t)b * NS + s] = w;
        ss[s] = allm ? 0.0f : sms[s];
    }
    __syncthreads();

    // ctx: 4 independent accumulators (break the FMA RAW chain -> load-bound)
    const float* Hb = g_H + (size_t)b * NS * DS;
    {
        const int d = t & 63, part = t >> 6;
        const int s0 = part * 256;
        float a0 = 0.0f, a1 = 0.0f, a2 = 0.0f, a3 = 0.0f;
        #pragma unroll 4
        for (int s = s0; s < s0 + 256; s += 4) {
            a0 += aw[s + 0] * Hb[(size_t)(s + 0) * DS + d];
            a1 += aw[s + 1] * Hb[(size_t)(s + 1) * DS + d];
            a2 += aw[s + 2] * Hb[(size_t)(s + 2) * DS + d];
            a3 += aw[s + 3] * Hb[(size_t)(s + 3) * DS + d];
        }
        cpart[part][d] = (a0 + a1) + (a2 + a3);
    }
    __syncthreads();
    if (t < DS)
        out_ctx[(size_t)b * DS + t] =
            (cpart[0][t] + cpart[1][t]) + (cpart[2][t] + cpart[3][t]);

    for (int it = 0; it < KSEL; it++) {
        float bv = -INFINITY; int bi = 0x7fffffff;
        #pragma unroll
        for (int u = 0; u < 4; u++) {
            int s = t + 256 * u;
            float v = ss[s];
            if (v > bv || (v == bv && s < bi)) { bv = v; bi = s; }
        }
        red[t] = bv; redi[t] = bi;
        __syncthreads();
        for (int off = 128; off > 0; off >>= 1) {
            if (t < off) {
                float v2 = red[t + off]; int i2 = redi[t + off];
                if (v2 > red[t] || (v2 == red[t] && i2 < redi[t])) { red[t] = v2; redi[t] = i2; }
            }
            __syncthreads();
        }
        if (t == 0) { idxs[it] = redi[0]; ss[redi[0]] = -INFINITY; }
        __syncthreads();
    }

    for (int e = t; e < KSEL * DS; e += 256) {
        int j = e >> 6, d = e & 63;
        out_sel[((size_t)b * KSEL + j) * DS + d] = Hb[(size_t)idxs[j] * DS + d];
    }
}

// ============================================================================
extern "C" void kernel_launch(void* const* d_in, const int* in_sizes, int n_in,
                              void* d_out, int out_size) {
    const float* X    = (const float*)d_in[0];
    const float* mask = (const float*)d_in[1];
    const float* W1   = (const float*)d_in[2];
    const float* b1   = (const float*)d_in[3];
    const float* W2   = (const float*)d_in[4];
    const float* b2   = (const float*)d_in[5];
    const float* q    = (const float*)d_in[6];

    float* out      = (float*)d_out;
    float* out_sel  = out;
    float* out_ctx  = out + (size_t)NB * KSEL * DS;
    float* out_attn = out_ctx + (size_t)NB * DS;

    cudaFuncSetAttribute(k1_mlp, cudaFuncAttributeMaxDynamicSharedMemorySize, SM_TOTAL);

    // 4 launches/call so ncu (-s 5 -c 1) profiles launch #6 = k1_mlp (part a)
    k0_setup<<<4, 256>>>(W1, b1, W2, b2, q);
    k1_mlp<<<4096, 256, SM_TOTAL>>>(X, 0);
    k1_mlp<<<4096, 256, SM_TOTAL>>>(X, 4096);
    k2_attn<<<NB, 256>>>(mask, out_sel, out_ctx, out_attn);
}

// round 15
// speedup vs baseline: 3.6161x; 1.1042x over previous
#include <cuda_runtime.h>
#include <cuda_fp16.h>
#include <stdint.h>
#include <math.h>

#define NB 1024
#define NS 1024
#define DI 128
#define DS 64
#define KSEL 8

typedef unsigned long long ull;

__device__ __half g_Hh[(size_t)NB * NS * DS];     // 128 MB (fp16 H)
__device__ float g_scores[(size_t)NB * NS];       // 4 MB

// pre-split, pre-swizzled weights (written once per call by k0_setup)
__device__ uint4 g_w1h[1024], g_w1l[1024];        // 16 KB each
__device__ uint4 g_w2h[512],  g_w2l[512];         // 8 KB each
__device__ float g_wt[65];                        // w~ = W2*qm, [64] = b2.qm
__device__ float g_b1s[64], g_b2s[64];

// ======================= helpers =======================
__device__ __forceinline__ uint32_t smem_u32(const void* p) {
    uint32_t a;
    asm("{ .reg .u64 t; cvta.to.shared.u64 t, %1; cvt.u32.u64 %0, t; }" : "=r"(a) : "l"(p));
    return a;
}
// 2-way fp16 split: fp32 pair -> packed half2 (hi, lo residual). 22 mantissa
// bits; 3-term product error ~2^-22 (fp32-class for this problem).
__device__ __forceinline__ void split2h(float a, float b, uint32_t& hi, uint32_t& lo) {
    __half2 h = __float22half2_rn(make_float2(a, b));
    float2 hf = __half22float2(h);
    __half2 l = __float22half2_rn(make_float2(a - hf.x, b - hf.y));
    hi = *reinterpret_cast<uint32_t*>(&h);
    lo = *reinterpret_cast<uint32_t*>(&l);
}
__device__ __forceinline__ void ldm4(uint32_t r[4], uint32_t addr) {
    asm volatile("ldmatrix.sync.aligned.m8n8.x4.shared.b16 {%0,%1,%2,%3}, [%4];"
        : "=r"(r[0]), "=r"(r[1]), "=r"(r[2]), "=r"(r[3]) : "r"(addr));
}
__device__ __forceinline__ void mma16816(float c[4], const uint32_t a[4],
                                         uint32_t b0, uint32_t b1) {
    asm volatile(
        "mma.sync.aligned.m16n8k16.row.col.f32.f16.f16.f32 "
        "{%0,%1,%2,%3}, {%4,%5,%6,%7}, {%8,%9}, {%0,%1,%2,%3};"
        : "+f"(c[0]), "+f"(c[1]), "+f"(c[2]), "+f"(c[3])
        : "r"(a[0]), "r"(a[1]), "r"(a[2]), "r"(a[3]), "r"(b0), "r"(b1));
}

// ======================= K0: one-time weight split =======================
__global__ __launch_bounds__(256) void k0_setup(
    const float* __restrict__ W1, const float* __restrict__ b1,
    const float* __restrict__ W2, const float* __restrict__ b2,
    const float* __restrict__ q)
{
    const int tid = threadIdx.x, blk = blockIdx.x;
    {   // W1 -> [n][128k] split tiles, swizzled (idx = n*16 + (kc^(n&7)))
        int task = blk * 256 + tid;
        int n = task & 63, kc = task >> 6;
        uint32_t h[4], l[4];
        #pragma unroll
        for (int j = 0; j < 4; j++) {
            float v0 = W1[(size_t)(kc * 8 + j * 2 + 0) * DS + n];
            float v1 = W1[(size_t)(kc * 8 + j * 2 + 1) * DS + n];
            split2h(v0, v1, h[j], l[j]);
        }
        int idx = n * 16 + (kc ^ (n & 7));
        g_w1h[idx] = make_uint4(h[0], h[1], h[2], h[3]);
        g_w1l[idx] = make_uint4(l[0], l[1], l[2], l[3]);
    }
    if (tid < 128) {   // W2 -> [n][64k] (idx = n*8 + (kc^(n&7)))
        int task = blk * 128 + tid;
        int n = task & 63, kc = task >> 6;
        uint32_t h[4], l[4];
        #pragma unroll
        for (int j = 0; j < 4; j++) {
            float v0 = W2[(size_t)(kc * 8 + j * 2 + 0) * DS + n];
            float v1 = W2[(size_t)(kc * 8 + j * 2 + 1) * DS + n];
            split2h(v0, v1, h[j], l[j]);
        }
        int idx = n * 8 + (kc ^ (n & 7));
        g_w2h[idx] = make_uint4(h[0], h[1], h[2], h[3]);
        g_w2l[idx] = make_uint4(l[0], l[1], l[2], l[3]);
    }
    if (blk == 0) {
        if (tid < DS) {
            g_b1s[tid] = b1[tid];
            g_b2s[tid] = b2[tid];
            float acc = 0.0f;
            #pragma unroll 8
            for (int d = 0; d < DS; d++)
                acc += W2[(size_t)tid * DS + d] * (0.5f * (q[d] + q[DS + d]));
            g_wt[tid] = acc;
        } else if (tid == 64) {
            float acc = 0.0f;
            #pragma unroll 8
            for (int d = 0; d < DS; d++)
                acc += b2[d] * (0.5f * (q[d] + q[DS + d]));
            g_wt[64] = acc;
        }
    }
}

// ======================= K1: register-resident split-fp16 HMMA MLP ==========
static constexpr int SM_W1H = 0,     SM_W1L = 16384;
static constexpr int SM_W2H = 32768, SM_W2L = 40960;
static constexpr int SM_WT = 49152,  SM_B1S = 49424, SM_B2S = 49680;
static constexpr int SM_TOTAL = 49936;

__global__ __launch_bounds__(256, 2) void k1_mlp(
    const float* __restrict__ X, int blk0)
{
    extern __shared__ __align__(16) char sm[];
    const uint32_t sb = smem_u32(sm);
    float* wt  = (float*)(sm + SM_WT);
    float* b1s = (float*)(sm + SM_B1S);
    float* b2s = (float*)(sm + SM_B2S);

    const int tid  = threadIdx.x;
    const int warp = tid >> 5, lane = tid & 31;
    const int grp  = lane >> 2, qd = lane & 3;
    const int seg  = lane >> 3, ri = lane & 7;
    const int rA = warp * 16 + grp, rB = rA + 8;
    const size_t row0 = (size_t)(blockIdx.x + blk0) * 128;

    // ---- prologue: L2-hot copy of pre-split weights into smem ----
    #pragma unroll
    for (int i = 0; i < 4; i++) {
        int idx = tid + 256 * i;
        ((uint4*)(sm + SM_W1H))[idx] = g_w1h[idx];
        ((uint4*)(sm + SM_W1L))[idx] = g_w1l[idx];
    }
    #pragma unroll
    for (int i = 0; i < 2; i++) {
        int idx = tid + 256 * i;
        ((uint4*)(sm + SM_W2H))[idx] = g_w2h[idx];
        ((uint4*)(sm + SM_W2L))[idx] = g_w2l[idx];
    }
    if (tid < 65) wt[tid] = g_wt[tid];
    if (tid < 64) { b1s[tid] = g_b1s[tid]; b2s[tid] = g_b2s[tid]; }

    const float* XrA = X + (row0 + rA) * DI + 2 * qd;
    const float* XrB = X + (row0 + rB) * DI + 2 * qd;

    float2 pa0 = *(const float2*)(XrA);
    float2 pb0 = *(const float2*)(XrB);
    float2 pa8 = *(const float2*)(XrA + 8);
    float2 pb8 = *(const float2*)(XrB + 8);

    __syncthreads();   // the ONLY barrier

    float c1[8][4];
    #pragma unroll
    for (int nt = 0; nt < 8; nt++)
        #pragma unroll
        for (int j = 0; j < 4; j++) c1[nt][j] = 0.0f;

    // ================= GEMM1: K=128, 8 chunks, 3 terms =================
    #pragma unroll
    for (int ks = 0; ks < 8; ks++) {
        float2 ca0 = pa0, cb0 = pb0, ca8 = pa8, cb8 = pb8;
        if (ks < 7) {
            int o = 16 * (ks + 1);
            pa0 = *(const float2*)(XrA + o);
            pb0 = *(const float2*)(XrB + o);
            pa8 = *(const float2*)(XrA + o + 8);
            pb8 = *(const float2*)(XrB + o + 8);
        }
        uint32_t ah[4], al[4];
        split2h(ca0.x, ca0.y, ah[0], al[0]);
        split2h(cb0.x, cb0.y, ah[1], al[1]);
        split2h(ca8.x, ca8.y, ah[2], al[2]);
        split2h(cb8.x, cb8.y, ah[3], al[3]);

        uint32_t bh[16], bl[16];
        #pragma unroll
        for (int g = 0; g < 4; g++) {
            int n = (g * 2 + (seg >> 1)) * 8 + ri;
            int c = 2 * ks + (seg & 1);
            uint32_t off = (uint32_t)n * 256 + (uint32_t)((c ^ (n & 7)) << 4);
            ldm4(&bh[g * 4], sb + SM_W1H + off);
            ldm4(&bl[g * 4], sb + SM_W1L + off);
        }
        #pragma unroll
        for (int nt = 0; nt < 8; nt++)
            mma16816(c1[nt], ah, bh[nt * 2], bh[nt * 2 + 1]);
        #pragma unroll
        for (int nt = 0; nt < 8; nt++)
            mma16816(c1[nt], ah, bl[nt * 2], bl[nt * 2 + 1]);
        #pragma unroll
        for (int nt = 0; nt < 8; nt++)
            mma16816(c1[nt], al, bh[nt * 2], bh[nt * 2 + 1]);
    }

    // ---- relu + b1 -> fp32 scores (w~) + in-register fp16 T fragments ----
    uint32_t th01[8], th23[8], tl01[8], tl23[8];
    {
        float pA = 0.0f, pB = 0.0f;
        #pragma unroll
        for (int nt = 0; nt < 8; nt++) {
            int c0 = nt * 8 + qd * 2;
            float t0 = fmaxf(c1[nt][0] + b1s[c0],     0.0f);
            float t1 = fmaxf(c1[nt][1] + b1s[c0 + 1], 0.0f);
            float t2 = fmaxf(c1[nt][2] + b1s[c0],     0.0f);
            float t3 = fmaxf(c1[nt][3] + b1s[c0 + 1], 0.0f);
            pA += t0 * wt[c0] + t1 * wt[c0 + 1];
            pB += t2 * wt[c0] + t3 * wt[c0 + 1];
            split2h(t0, t1, th01[nt], tl01[nt]);
            split2h(t2, t3, th23[nt], tl23[nt]);
        }
        pA += __shfl_xor_sync(0xffffffffu, pA, 1);
        pA += __shfl_xor_sync(0xffffffffu, pA, 2);
        pB += __shfl_xor_sync(0xffffffffu, pB, 1);
        pB += __shfl_xor_sync(0xffffffffu, pB, 2);
        if (qd == 0) {
            float b2qm = wt[64];
            g_scores[row0 + rA] = (pA + b2qm) * 0.125f;
            g_scores[row0 + rB] = (pB + b2qm) * 0.125f;
        }
    }

    // ================= GEMM2: H = T @ W2 + b2 (K=64, T in registers) =========
    float c2[8][4];
    #pragma unroll
    for (int nt = 0; nt < 8; nt++)
        #pragma unroll
        for (int j = 0; j < 4; j++) c2[nt][j] = 0.0f;

    #pragma unroll
    for (int ks = 0; ks < 4; ks++) {
        uint32_t ah[4] = {th01[2 * ks], th23[2 * ks], th01[2 * ks + 1], th23[2 * ks + 1]};
        uint32_t al[4] = {tl01[2 * ks], tl23[2 * ks], tl01[2 * ks + 1], tl23[2 * ks + 1]};
        uint32_t bh[16], bl[16];
        #pragma unroll
        for (int g = 0; g < 4; g++) {
            int n = (g * 2 + (seg >> 1)) * 8 + ri;
            int c = 2 * ks + (seg & 1);
            uint32_t off = (uint32_t)n * 128 + (uint32_t)((c ^ (n & 7)) << 4);
            ldm4(&bh[g * 4], sb + SM_W2H + off);
            ldm4(&bl[g * 4], sb + SM_W2L + off);
        }
        #pragma unroll
        for (int nt = 0; nt < 8; nt++)
            mma16816(c2[nt], ah, bh[nt * 2], bh[nt * 2 + 1]);
        #pragma unroll
        for (int nt = 0; nt < 8; nt++)
            mma16816(c2[nt], ah, bl[nt * 2], bl[nt * 2 + 1]);
        #pragma unroll
        for (int nt = 0; nt < 8; nt++)
            mma16816(c2[nt], al, bh[nt * 2], bh[nt * 2 + 1]);
    }

    // ---- epilogue: +b2, fp16 H store (half2 per 2 cols) ----
    #pragma unroll
    for (int nt = 0; nt < 8; nt++) {
        int c0 = nt * 8 + qd * 2;
        __half2 hA = __floats2half2_rn(c2[nt][0] + b2s[c0], c2[nt][1] + b2s[c0 + 1]);
        __half2 hB = __floats2half2_rn(c2[nt][2] + b2s[c0], c2[nt][3] + b2s[c0 + 1]);
        *(__half2*)&g_Hh[(row0 + rA) * DS + c0] = hA;
        *(__half2*)&g_Hh[(row0 + rB) * DS + c0] = hB;
    }
}

// ======================= K2: softmax + ctx + top-8 + gather ==================
__global__ __launch_bounds__(256) void k2_attn(
    const float* __restrict__ mask,
    float* __restrict__ out_sel, float* __restrict__ out_ctx,
    float* __restrict__ out_attn)
{
    __shared__ float sms[NS];
    __shared__ float ss[NS];
    __shared__ float aw[NS];
    __shared__ float red[256];
    __shared__ int   redi[256];
    __shared__ float cpart[16][DS + 1];
    __shared__ int   idxs[KSEL];

    const int t = threadIdx.x;
    const int b = blockIdx.x;
    const float* sc = g_scores + (size_t)b * NS;
    const float* mk = mask + (size_t)b * NS;

    float lmax = -INFINITY;
    #pragma unroll
    for (int u = 0; u < 4; u++) {
        int s = t + 256 * u;
        float v = sc[s];
        float m = (mk[s] > 0.5f) ? v : -INFINITY;
        sms[s] = m;
        lmax = fmaxf(lmax, m);
    }
    red[t] = lmax;
    __syncthreads();
    for (int off = 128; off > 0; off >>= 1) {
        if (t < off) red[t] = fmaxf(red[t], red[t + off]);
        __syncthreads();
    }
    const float mx = red[0];
    const bool allm = !(mx > -INFINITY);
    __syncthreads();

    float lsum = 0.0f;
    #pragma unroll
    for (int u = 0; u < 4; u++) {
        int s = t + 256 * u;
        float m = sms[s];
        float e;
        if (allm)                e = 1.0f;
        else if (m == -INFINITY) e = 0.0f;
        else                     e = expf(m - mx);
        aw[s] = e;
        lsum += e;
    }
    red[t] = lsum;
    __syncthreads();
    for (int off = 128; off > 0; off >>= 1) {
        if (t < off) red[t] += red[t + off];
        __syncthreads();
    }
    const float inv = 1.0f / red[0];
    __syncthreads();
    #pragma unroll
    for (int u = 0; u < 4; u++) {
        int s = t + 256 * u;
        float w = aw[s] * inv;
        aw[s] = w;
        out_attn[(size_t)b * NS + s] = w;
        ss[s] = allm ? 0.0f : sms[s];
    }
    __syncthreads();

    // ctx: fp16 H, 8B loads, 16 s-parts x 16 d-groups of 4, 8 indep FMA chains
    const __half* Hb = g_Hh + (size_t)b * NS * DS;
    {
        const int part = t >> 4, dg = t & 15;      // s-part 0..15, d-group 0..15
        const int s0 = part * 64;
        const uint2* src = (const uint2*)(Hb + (size_t)s0 * DS + dg * 4);
        float a00 = 0.f, a01 = 0.f, a02 = 0.f, a03 = 0.f;
        float a10 = 0.f, a11 = 0.f, a12 = 0.f, a13 = 0.f;
        #pragma unroll 8
        for (int i = 0; i < 64; i += 2) {
            uint2 v0 = src[(size_t)i * 16];        // DS/4 halves = 16 uint2 per row
            uint2 v1 = src[(size_t)(i + 1) * 16];
            float w0 = aw[s0 + i], w1 = aw[s0 + i + 1];
            float2 p00 = __half22float2(*(__half2*)&v0.x);
            float2 p01 = __half22float2(*(__half2*)&v0.y);
            float2 p10 = __half22float2(*(__half2*)&v1.x);
            float2 p11 = __half22float2(*(__half2*)&v1.y);
            a00 += w0 * p00.x; a01 += w0 * p00.y;
            a02 += w0 * p01.x; a03 += w0 * p01.y;
            a10 += w1 * p10.x; a11 += w1 * p10.y;
            a12 += w1 * p11.x; a13 += w1 * p11.y;
        }
        cpart[part][dg * 4 + 0] = a00 + a10;
        cpart[part][dg * 4 + 1] = a01 + a11;
        cpart[part][dg * 4 + 2] = a02 + a12;
        cpart[part][dg * 4 + 3] = a03 + a13;
    }
    __syncthreads();
    if (t < DS) {
        float acc = 0.0f;
        #pragma unroll
        for (int p = 0; p < 16; p++) acc += cpart[p][t];
        out_ctx[(size_t)b * DS + t] = acc;
    }

    for (int it = 0; it < KSEL; it++) {
        float bv = -INFINITY; int bi = 0x7fffffff;
        #pragma unroll
        for (int u = 0; u < 4; u++) {
            int s = t + 256 * u;
            float v = ss[s];
            if (v > bv || (v == bv && s < bi)) { bv = v; bi = s; }
        }
        red[t] = bv; redi[t] = bi;
        __syncthreads();
        for (int off = 128; off > 0; off >>= 1) {
            if (t < off) {
                float v2 = red[t + off]; int i2 = redi[t + off];
                if (v2 > red[t] || (v2 == red[t] && i2 < redi[t])) { red[t] = v2; redi[t] = i2; }
            }
            __syncthreads();
        }
        if (t == 0) { idxs[it] = redi[0]; ss[redi[0]] = -INFINITY; }
        __syncthreads();
    }

    for (int e = t; e < KSEL * DS; e += 256) {
        int j = e >> 6, d = e & 63;
        out_sel[((size_t)b * KSEL + j) * DS + d] =
            __half2float(Hb[(size_t)idxs[j] * DS + d]);
    }
}

// ============================================================================
extern "C" void kernel_launch(void* const* d_in, const int* in_sizes, int n_in,
                              void* d_out, int out_size) {
    const float* X    = (const float*)d_in[0];
    const float* mask = (const float*)d_in[1];
    const float* W1   = (const float*)d_in[2];
    const float* b1   = (const float*)d_in[3];
    const float* W2   = (const float*)d_in[4];
    const float* b2   = (const float*)d_in[5];
    const float* q    = (const float*)d_in[6];

    float* out      = (float*)d_out;
    float* out_sel  = out;
    float* out_ctx  = out + (size_t)NB * KSEL * DS;
    float* out_attn = out_ctx + (size_t)NB * DS;

    cudaFuncSetAttribute(k1_mlp, cudaFuncAttributeMaxDynamicSharedMemorySize, SM_TOTAL);

    k0_setup<<<4, 256>>>(W1, b1, W2, b2, q);
    k1_mlp<<<4096, 256, SM_TOTAL>>>(X, 0);
    k1_mlp<<<4096, 256, SM_TOTAL>>>(X, 4096);
    k2_attn<<<NB, 256>>>(mask, out_sel, out_ctx, out_attn);
}

// round 16
// speedup vs baseline: 3.6849x; 1.0190x over previous
#include <cuda_runtime.h>
#include <cuda_fp16.h>
#include <stdint.h>
#include <math.h>

#define NB 1024
#define NS 1024
#define DI 128
#define DS 64
#define KSEL 8

typedef unsigned long long ull;

__device__ __half g_Hh[(size_t)NB * NS * DS];     // 128 MB (fp16 H)
__device__ float g_scores[(size_t)NB * NS];       // 4 MB

// pre-split, pre-swizzled weights (written once per call by k0_setup)
__device__ uint4 g_w1h[1024], g_w1l[1024];        // 16 KB each
__device__ uint4 g_w2h[512],  g_w2l[512];         // 8 KB each
__device__ float g_wt[65];                        // w~ = W2*qm, [64] = b2.qm
__device__ float g_b1s[64], g_b2s[64];

// ======================= helpers =======================
__device__ __forceinline__ uint32_t smem_u32(const void* p) {
    uint32_t a;
    asm("{ .reg .u64 t; cvta.to.shared.u64 t, %1; cvt.u32.u64 %0, t; }" : "=r"(a) : "l"(p));
    return a;
}
// 2-way fp16 split: fp32 pair -> packed half2 (hi, lo residual). 22 mantissa
// bits; 3-term product error ~2^-22 (fp32-class for this problem).
__device__ __forceinline__ void split2h(float a, float b, uint32_t& hi, uint32_t& lo) {
    __half2 h = __float22half2_rn(make_float2(a, b));
    float2 hf = __half22float2(h);
    __half2 l = __float22half2_rn(make_float2(a - hf.x, b - hf.y));
    hi = *reinterpret_cast<uint32_t*>(&h);
    lo = *reinterpret_cast<uint32_t*>(&l);
}
__device__ __forceinline__ void ldm4(uint32_t r[4], uint32_t addr) {
    asm volatile("ldmatrix.sync.aligned.m8n8.x4.shared.b16 {%0,%1,%2,%3}, [%4];"
        : "=r"(r[0]), "=r"(r[1]), "=r"(r[2]), "=r"(r[3]) : "r"(addr));
}
__device__ __forceinline__ void mma16816(float c[4], const uint32_t a[4],
                                         uint32_t b0, uint32_t b1) {
    asm volatile(
        "mma.sync.aligned.m16n8k16.row.col.f32.f16.f16.f32 "
        "{%0,%1,%2,%3}, {%4,%5,%6,%7}, {%8,%9}, {%0,%1,%2,%3};"
        : "+f"(c[0]), "+f"(c[1]), "+f"(c[2]), "+f"(c[3])
        : "r"(a[0]), "r"(a[1]), "r"(a[2]), "r"(a[3]), "r"(b0), "r"(b1));
}

// ======================= K0: one-time weight split =======================
__global__ __launch_bounds__(256) void k0_setup(
    const float* __restrict__ W1, const float* __restrict__ b1,
    const float* __restrict__ W2, const float* __restrict__ b2,
    const float* __restrict__ q)
{
    const int tid = threadIdx.x, blk = blockIdx.x;
    {   // W1 -> [n][128k] split tiles, swizzled (idx = n*16 + (kc^(n&7)))
        int task = blk * 256 + tid;
        int n = task & 63, kc = task >> 6;
        uint32_t h[4], l[4];
        #pragma unroll
        for (int j = 0; j < 4; j++) {
            float v0 = W1[(size_t)(kc * 8 + j * 2 + 0) * DS + n];
            float v1 = W1[(size_t)(kc * 8 + j * 2 + 1) * DS + n];
            split2h(v0, v1, h[j], l[j]);
        }
        int idx = n * 16 + (kc ^ (n & 7));
        g_w1h[idx] = make_uint4(h[0], h[1], h[2], h[3]);
        g_w1l[idx] = make_uint4(l[0], l[1], l[2], l[3]);
    }
    if (tid < 128) {   // W2 -> [n][64k] (idx = n*8 + (kc^(n&7)))
        int task = blk * 128 + tid;
        int n = task & 63, kc = task >> 6;
        uint32_t h[4], l[4];
        #pragma unroll
        for (int j = 0; j < 4; j++) {
            float v0 = W2[(size_t)(kc * 8 + j * 2 + 0) * DS + n];
            float v1 = W2[(size_t)(kc * 8 + j * 2 + 1) * DS + n];
            split2h(v0, v1, h[j], l[j]);
        }
        int idx = n * 8 + (kc ^ (n & 7));
        g_w2h[idx] = make_uint4(h[0], h[1], h[2], h[3]);
        g_w2l[idx] = make_uint4(l[0], l[1], l[2], l[3]);
    }
    if (blk == 0) {
        if (tid < DS) {
            g_b1s[tid] = b1[tid];
            g_b2s[tid] = b2[tid];
            float acc = 0.0f;
            #pragma unroll 8
            for (int d = 0; d < DS; d++)
                acc += W2[(size_t)tid * DS + d] * (0.5f * (q[d] + q[DS + d]));
            g_wt[tid] = acc;
        } else if (tid == 64) {
            float acc = 0.0f;
            #pragma unroll 8
            for (int d = 0; d < DS; d++)
                acc += b2[d] * (0.5f * (q[d] + q[DS + d]));
            g_wt[64] = acc;
        }
    }
}

// ======================= K1: register-resident split-fp16 HMMA MLP ==========
// GEMM1: 3-term split (scores need fp32-class T).
// GEMM2: 2-term (Th x (W2h + W2l)) — H tolerance is 1e-3; T-residual dropped.
static constexpr int SM_W1H = 0,     SM_W1L = 16384;
static constexpr int SM_W2H = 32768, SM_W2L = 40960;
static constexpr int SM_WT = 49152,  SM_B1S = 49424, SM_B2S = 49680;
static constexpr int SM_TOTAL = 49936;

__global__ __launch_bounds__(256, 2) void k1_mlp(
    const float* __restrict__ X)
{
    extern __shared__ __align__(16) char sm[];
    const uint32_t sb = smem_u32(sm);
    float* wt  = (float*)(sm + SM_WT);
    float* b1s = (float*)(sm + SM_B1S);
    float* b2s = (float*)(sm + SM_B2S);

    const int tid  = threadIdx.x;
    const int warp = tid >> 5, lane = tid & 31;
    const int grp  = lane >> 2, qd = lane & 3;
    const int seg  = lane >> 3, ri = lane & 7;
    const int rA = warp * 16 + grp, rB = rA + 8;
    const size_t row0 = (size_t)blockIdx.x * 128;

    // ---- prologue: L2-hot copy of pre-split weights into smem ----
    #pragma unroll
    for (int i = 0; i < 4; i++) {
        int idx = tid + 256 * i;
        ((uint4*)(sm + SM_W1H))[idx] = g_w1h[idx];
        ((uint4*)(sm + SM_W1L))[idx] = g_w1l[idx];
    }
    #pragma unroll
    for (int i = 0; i < 2; i++) {
        int idx = tid + 256 * i;
        ((uint4*)(sm + SM_W2H))[idx] = g_w2h[idx];
        ((uint4*)(sm + SM_W2L))[idx] = g_w2l[idx];
    }
    if (tid < 65) wt[tid] = g_wt[tid];
    if (tid < 64) { b1s[tid] = g_b1s[tid]; b2s[tid] = g_b2s[tid]; }

    const float* XrA = X + (row0 + rA) * DI + 2 * qd;
    const float* XrB = X + (row0 + rB) * DI + 2 * qd;

    float2 pa0 = *(const float2*)(XrA);
    float2 pb0 = *(const float2*)(XrB);
    float2 pa8 = *(const float2*)(XrA + 8);
    float2 pb8 = *(const float2*)(XrB + 8);

    __syncthreads();   // the ONLY barrier

    float c1[8][4];
    #pragma unroll
    for (int nt = 0; nt < 8; nt++)
        #pragma unroll
        for (int j = 0; j < 4; j++) c1[nt][j] = 0.0f;

    // ================= GEMM1: K=128, 8 chunks, 3 terms =================
    #pragma unroll
    for (int ks = 0; ks < 8; ks++) {
        float2 ca0 = pa0, cb0 = pb0, ca8 = pa8, cb8 = pb8;
        if (ks < 7) {
            int o = 16 * (ks + 1);
            pa0 = *(const float2*)(XrA + o);
            pb0 = *(const float2*)(XrB + o);
            pa8 = *(const float2*)(XrA + o + 8);
            pb8 = *(const float2*)(XrB + o + 8);
        }
        uint32_t ah[4], al[4];
        split2h(ca0.x, ca0.y, ah[0], al[0]);
        split2h(cb0.x, cb0.y, ah[1], al[1]);
        split2h(ca8.x, ca8.y, ah[2], al[2]);
        split2h(cb8.x, cb8.y, ah[3], al[3]);

        uint32_t bh[16], bl[16];
        #pragma unroll
        for (int g = 0; g < 4; g++) {
            int n = (g * 2 + (seg >> 1)) * 8 + ri;
            int c = 2 * ks + (seg & 1);
            uint32_t off = (uint32_t)n * 256 + (uint32_t)((c ^ (n & 7)) << 4);
            ldm4(&bh[g * 4], sb + SM_W1H + off);
            ldm4(&bl[g * 4], sb + SM_W1L + off);
        }
        #pragma unroll
        for (int nt = 0; nt < 8; nt++)
            mma16816(c1[nt], ah, bh[nt * 2], bh[nt * 2 + 1]);
        #pragma unroll
        for (int nt = 0; nt < 8; nt++)
            mma16816(c1[nt], ah, bl[nt * 2], bl[nt * 2 + 1]);
        #pragma unroll
        for (int nt = 0; nt < 8; nt++)
            mma16816(c1[nt], al, bh[nt * 2], bh[nt * 2 + 1]);
    }

    // ---- relu + b1 -> fp32 scores (w~) + fp16 T fragments (hi only) ----
    uint32_t th01[8], th23[8];
    {
        float pA = 0.0f, pB = 0.0f;
        #pragma unroll
        for (int nt = 0; nt < 8; nt++) {
            int c0 = nt * 8 + qd * 2;
            float t0 = fmaxf(c1[nt][0] + b1s[c0],     0.0f);
            float t1 = fmaxf(c1[nt][1] + b1s[c0 + 1], 0.0f);
            float t2 = fmaxf(c1[nt][2] + b1s[c0],     0.0f);
            float t3 = fmaxf(c1[nt][3] + b1s[c0 + 1], 0.0f);
            pA += t0 * wt[c0] + t1 * wt[c0 + 1];
            pB += t2 * wt[c0] + t3 * wt[c0 + 1];
            __half2 h01 = __floats2half2_rn(t0, t1);
            __half2 h23 = __floats2half2_rn(t2, t3);
            th01[nt] = *reinterpret_cast<uint32_t*>(&h01);
            th23[nt] = *reinterpret_cast<uint32_t*>(&h23);
        }
        pA += __shfl_xor_sync(0xffffffffu, pA, 1);
        pA += __shfl_xor_sync(0xffffffffu, pA, 2);
        pB += __shfl_xor_sync(0xffffffffu, pB, 1);
        pB += __shfl_xor_sync(0xffffffffu, pB, 2);
        if (qd == 0) {
            float b2qm = wt[64];
            g_scores[row0 + rA] = (pA + b2qm) * 0.125f;
            g_scores[row0 + rB] = (pB + b2qm) * 0.125f;
        }
    }

    // ====== GEMM2: H = Th @ (W2h + W2l) + b2 (K=64, 2 terms, T in regs) ======
    float c2[8][4];
    #pragma unroll
    for (int nt = 0; nt < 8; nt++)
        #pragma unroll
        for (int j = 0; j < 4; j++) c2[nt][j] = 0.0f;

    #pragma unroll
    for (int ks = 0; ks < 4; ks++) {
        uint32_t ah[4] = {th01[2 * ks], th23[2 * ks], th01[2 * ks + 1], th23[2 * ks + 1]};
        uint32_t bh[16], bl[16];
        #pragma unroll
        for (int g = 0; g < 4; g++) {
            int n = (g * 2 + (seg >> 1)) * 8 + ri;
            int c = 2 * ks + (seg & 1);
            uint32_t off = (uint32_t)n * 128 + (uint32_t)((c ^ (n & 7)) << 4);
            ldm4(&bh[g * 4], sb + SM_W2H + off);
            ldm4(&bl[g * 4], sb + SM_W2L + off);
        }
        #pragma unroll
        for (int nt = 0; nt < 8; nt++)
            mma16816(c2[nt], ah, bh[nt * 2], bh[nt * 2 + 1]);
        #pragma unroll
        for (int nt = 0; nt < 8; nt++)
            mma16816(c2[nt], ah, bl[nt * 2], bl[nt * 2 + 1]);
    }

    // ---- epilogue: +b2, fp16 H store (half2 per 2 cols) ----
    #pragma unroll
    for (int nt = 0; nt < 8; nt++) {
        int c0 = nt * 8 + qd * 2;
        __half2 hA = __floats2half2_rn(c2[nt][0] + b2s[c0], c2[nt][1] + b2s[c0 + 1]);
        __half2 hB = __floats2half2_rn(c2[nt][2] + b2s[c0], c2[nt][3] + b2s[c0 + 1]);
        *(__half2*)&g_Hh[(row0 + rA) * DS + c0] = hA;
        *(__half2*)&g_Hh[(row0 + rB) * DS + c0] = hB;
    }
}

// ======================= K2: softmax + ctx + top-8 + gather ==================
__global__ __launch_bounds__(256) void k2_attn(
    const float* __restrict__ mask,
    float* __restrict__ out_sel, float* __restrict__ out_ctx,
    float* __restrict__ out_attn)
{
    __shared__ float sms[NS];
    __shared__ float ss[NS];
    __shared__ float aw[NS];
    __shared__ float red[256];
    __shared__ int   redi[256];
    __shared__ float cpart[16][DS + 1];
    __shared__ int   idxs[KSEL];

    const int t = threadIdx.x;
    const int b = blockIdx.x;
    const float* sc = g_scores + (size_t)b * NS;
    const float* mk = mask + (size_t)b * NS;

    float lmax = -INFINITY;
    #pragma unroll
    for (int u = 0; u < 4; u++) {
        int s = t + 256 * u;
        float v = sc[s];
        float m = (mk[s] > 0.5f) ? v : -INFINITY;
        sms[s] = m;
        lmax = fmaxf(lmax, m);
    }
    red[t] = lmax;
    __syncthreads();
    for (int off = 128; off > 0; off >>= 1) {
        if (t < off) red[t] = fmaxf(red[t], red[t + off]);
        __syncthreads();
    }
    const float mx = red[0];
    const bool allm = !(mx > -INFINITY);
    __syncthreads();

    float lsum = 0.0f;
    #pragma unroll
    for (int u = 0; u < 4; u++) {
        int s = t + 256 * u;
        float m = sms[s];
        float e;
        if (allm)                e = 1.0f;
        else if (m == -INFINITY) e = 0.0f;
        else                     e = expf(m - mx);
        aw[s] = e;
        lsum += e;
    }
    red[t] = lsum;
    __syncthreads();
    for (int off = 128; off > 0; off >>= 1) {
        if (t < off) red[t] += red[t + off];
        __syncthreads();
    }
    const float inv = 1.0f / red[0];
    __syncthreads();
    #pragma unroll
    for (int u = 0; u < 4; u++) {
        int s = t + 256 * u;
        float w = aw[s] * inv;
        aw[s] = w;
        out_attn[(size_t)b * NS + s] = w;
        ss[s] = allm ? 0.0f : sms[s];
    }
    __syncthreads();

    // ctx: fp16 H, 8B loads, 16 s-parts x 16 d-groups of 4, 8 indep FMA chains
    const __half* Hb = g_Hh + (size_t)b * NS * DS;
    {
        const int part = t >> 4, dg = t & 15;
        const int s0 = part * 64;
        const uint2* src = (const uint2*)(Hb + (size_t)s0 * DS + dg * 4);
        float a00 = 0.f, a01 = 0.f, a02 = 0.f, a03 = 0.f;
        float a10 = 0.f, a11 = 0.f, a12 = 0.f, a13 = 0.f;
        #pragma unroll 8
        for (int i = 0; i < 64; i += 2) {
            uint2 v0 = src[(size_t)i * 16];
            uint2 v1 = src[(size_t)(i + 1) * 16];
            float w0 = aw[s0 + i], w1 = aw[s0 + i + 1];
            float2 p00 = __half22float2(*(__half2*)&v0.x);
            float2 p01 = __half22float2(*(__half2*)&v0.y);
            float2 p10 = __half22float2(*(__half2*)&v1.x);
            float2 p11 = __half22float2(*(__half2*)&v1.y);
            a00 += w0 * p00.x; a01 += w0 * p00.y;
            a02 += w0 * p01.x; a03 += w0 * p01.y;
            a10 += w1 * p10.x; a11 += w1 * p10.y;
            a12 += w1 * p11.x; a13 += w1 * p11.y;
        }
        cpart[part][dg * 4 + 0] = a00 + a10;
        cpart[part][dg * 4 + 1] = a01 + a11;
        cpart[part][dg * 4 + 2] = a02 + a12;
        cpart[part][dg * 4 + 3] = a03 + a13;
    }
    __syncthreads();
    if (t < DS) {
        float acc = 0.0f;
        #pragma unroll
        for (int p = 0; p < 16; p++) acc += cpart[p][t];
        out_ctx[(size_t)b * DS + t] = acc;
    }

    for (int it = 0; it < KSEL; it++) {
        float bv = -INFINITY; int bi = 0x7fffffff;
        #pragma unroll
        for (int u = 0; u < 4; u++) {
            int s = t + 256 * u;
            float v = ss[s];
            if (v > bv || (v == bv && s < bi)) { bv = v; bi = s; }
        }
        red[t] = bv; redi[t] = bi;
        __syncthreads();
        for (int off = 128; off > 0; off >>= 1) {
            if (t < off) {
                float v2 = red[t + off]; int i2 = redi[t + off];
                if (v2 > red[t] || (v2 == red[t] && i2 < redi[t])) { red[t] = v2; redi[t] = i2; }
            }
            __syncthreads();
        }
        if (t == 0) { idxs[it] = redi[0]; ss[redi[0]] = -INFINITY; }
        __syncthreads();
    }

    for (int e = t; e < KSEL * DS; e += 256) {
        int j = e >> 6, d = e & 63;
        out_sel[((size_t)b * KSEL + j) * DS + d] =
            __half2float(Hb[(size_t)idxs[j] * DS + d]);
    }
}

// ============================================================================
extern "C" void kernel_launch(void* const* d_in, const int* in_sizes, int n_in,
                              void* d_out, int out_size) {
    const float* X    = (const float*)d_in[0];
    const float* mask = (const float*)d_in[1];
    const float* W1   = (const float*)d_in[2];
    const float* b1   = (const float*)d_in[3];
    const float* W2   = (const float*)d_in[4];
    const float* b2   = (const float*)d_in[5];
    const float* q    = (const float*)d_in[6];

    float* out      = (float*)d_out;
    float* out_sel  = out;
    float* out_ctx  = out + (size_t)NB * KSEL * DS;
    float* out_attn = out_ctx + (size_t)NB * DS;

    cudaFuncSetAttribute(k1_mlp, cudaFuncAttributeMaxDynamicSharedMemorySize, SM_TOTAL);

    k0_setup<<<4, 256>>>(W1, b1, W2, b2, q);
    k1_mlp<<<8192, 256, SM_TOTAL>>>(X);
    k2_attn<<<NB, 256>>>(mask, out_sel, out_ctx, out_attn);
}